// round 7
// baseline (speedup 1.0000x reference)
#include <cuda_runtime.h>
#include <cuda_bf16.h>
#include <cstdint>

#define B_SZ   2
#define T_SZ   2048
#define C_SZ   1024
#define M_ROWS 4096
#define N_QKV  3072
#define GEMM_K 1024

// ---------------------------------------------------------------------------
// Scratch (__device__ globals; no allocation allowed)
// ---------------------------------------------------------------------------
__device__ __nv_bfloat16 g_x_hi[M_ROWS * C_SZ];
__device__ __nv_bfloat16 g_x_lo[M_ROWS * C_SZ];
__device__ __nv_bfloat16 g_wq_hi[N_QKV * GEMM_K];   // transposed [n][k]
__device__ __nv_bfloat16 g_wq_lo[N_QKV * GEMM_K];
__device__ __nv_bfloat16 g_wp_hi[C_SZ * GEMM_K];    // transposed [n][k]
__device__ __nv_bfloat16 g_wp_lo[C_SZ * GEMM_K];
// qkv outputs, split bf16, [bh][t][d]
__device__ __nv_bfloat16 g_kh[32 * T_SZ * 64], g_kl[32 * T_SZ * 64];
__device__ __nv_bfloat16 g_qh[32 * T_SZ * 64], g_ql[32 * T_SZ * 64];
__device__ __nv_bfloat16 g_vh[32 * T_SZ * 64], g_vl[32 * T_SZ * 64];
// attention out, split bf16, [b][t][C]
__device__ __nv_bfloat16 g_ao_hi[M_ROWS * C_SZ], g_ao_lo[M_ROWS * C_SZ];

// ---------------------------------------------------------------------------
// PTX helpers (plain sm_103 target)
// ---------------------------------------------------------------------------
#define CP_ASYNC16(dst, src) \
    asm volatile("cp.async.cg.shared.global [%0], [%1], 16;" :: "r"(dst), "l"(src))
#define CP_COMMIT() asm volatile("cp.async.commit_group;" ::: "memory")
#define CP_WAIT1()  asm volatile("cp.async.wait_group 1;" ::: "memory")
#define CP_WAIT0()  asm volatile("cp.async.wait_group 0;" ::: "memory")

__device__ __forceinline__ void ldm_x4(uint32_t* r, uint32_t a) {
    asm volatile("ldmatrix.sync.aligned.m8n8.x4.shared.b16 {%0,%1,%2,%3}, [%4];"
                 : "=r"(r[0]), "=r"(r[1]), "=r"(r[2]), "=r"(r[3]) : "r"(a));
}
__device__ __forceinline__ void ldm_x4t(uint32_t* r, uint32_t a) {
    asm volatile("ldmatrix.sync.aligned.m8n8.x4.trans.shared.b16 {%0,%1,%2,%3}, [%4];"
                 : "=r"(r[0]), "=r"(r[1]), "=r"(r[2]), "=r"(r[3]) : "r"(a));
}
__device__ __forceinline__ void mma_bf16(float* d, const uint32_t* a,
                                         const uint32_t* b) {
    asm volatile(
        "mma.sync.aligned.m16n8k16.row.col.f32.bf16.bf16.f32 "
        "{%0,%1,%2,%3}, {%4,%5,%6,%7}, {%8,%9}, {%0,%1,%2,%3};"
        : "+f"(d[0]), "+f"(d[1]), "+f"(d[2]), "+f"(d[3])
        : "r"(a[0]), "r"(a[1]), "r"(a[2]), "r"(a[3]), "r"(b[0]), "r"(b[1]));
}
__device__ __forceinline__ uint32_t packbf(float lo, float hi) {
    __nv_bfloat162 t = __floats2bfloat162_rn(lo, hi);
    return *reinterpret_cast<uint32_t*>(&t);
}
__device__ __forceinline__ float lowf(uint32_t u)  { return __uint_as_float(u << 16); }
__device__ __forceinline__ float highf(uint32_t u) { return __uint_as_float(u & 0xFFFF0000u); }

// ---------------------------------------------------------------------------
// Prep: fp32 -> (hi, lo) bf16
// ---------------------------------------------------------------------------
__global__ __launch_bounds__(256)
void split_x_kernel(const float* __restrict__ in) {
    int i = blockIdx.x * 256 + threadIdx.x;
    float v = in[i];
    __nv_bfloat16 h = __float2bfloat16(v);
    g_x_hi[i] = h;
    g_x_lo[i] = __float2bfloat16(v - __bfloat162float(h));
}

__global__ void tsplit_kernel(const float* __restrict__ w, int N, int mode) {
    __shared__ float tile[32][33];
    const int nb = blockIdx.x * 32, kb = blockIdx.y * 32;
    const int tx = threadIdx.x, ty = threadIdx.y;   // (32, 8)
#pragma unroll
    for (int i2 = 0; i2 < 32; i2 += 8)
        tile[ty + i2][tx] = w[(size_t)(kb + ty + i2) * N + nb + tx];
    __syncthreads();
    __nv_bfloat16* oh = mode ? g_wp_hi : g_wq_hi;
    __nv_bfloat16* ol = mode ? g_wp_lo : g_wq_lo;
#pragma unroll
    for (int i2 = 0; i2 < 32; i2 += 8) {
        float v = tile[tx][ty + i2];
        __nv_bfloat16 h = __float2bfloat16(v);
        size_t o = (size_t)(nb + ty + i2) * GEMM_K + kb + tx;
        oh[o] = h;
        ol[o] = __float2bfloat16(v - __bfloat162float(h));
    }
}

// ---------------------------------------------------------------------------
// HMMA split-bf16 GEMM, 128x128 tile, BK=64, 3-stage cp.async pipeline.
// 512 threads = 16 warps in a 4x4 grid; 32x32 per warp (4 warps/SMSP for
// latency hiding; single-buffered fragments to stay under 128 regs).
// mode 0: epilogue bias + split-write into g_{k,q,v}{h,l}  [bh][t][d]
// mode 1: epilogue bias + fp32 store to out
// ---------------------------------------------------------------------------
#define G_ROWB   144                     // 128B data + 16B pad
#define G_TILE   (128 * G_ROWB)          // 18432 per variant
#define G_STAGE  (4 * G_TILE)            // 73728
#define GEMM_SMEM (3 * G_STAGE)          // 221184

__global__ __launch_bounds__(512, 1)
void gemm_hmma(const float* __restrict__ bias, float* __restrict__ out,
               int mode) {
    extern __shared__ char smem[];
    const uint32_t sbase = (uint32_t)__cvta_generic_to_shared(smem);
    const int tid = threadIdx.x;
    const int lane = tid & 31, warp = tid >> 5;
    const int wr = warp & 3, wc = warp >> 2;      // 4x4 warp grid
    const int rowBase = blockIdx.y * 128;
    const int colBase = blockIdx.x * 128;

    const __nv_bfloat16 *srcs[4];
    if (mode == 0) { srcs[0] = g_x_hi;  srcs[1] = g_x_lo;  srcs[2] = g_wq_hi; srcs[3] = g_wq_lo; }
    else           { srcs[0] = g_ao_hi; srcs[1] = g_ao_lo; srcs[2] = g_wp_hi; srcs[3] = g_wp_lo; }
    const int bases[4] = {rowBase, rowBase, colBase, colBase};

    float acc[2][4][4];
#pragma unroll
    for (int mt = 0; mt < 2; mt++)
#pragma unroll
        for (int nt = 0; nt < 4; nt++)
#pragma unroll
            for (int q = 0; q < 4; q++) acc[mt][nt][q] = 0.f;

    // per chunk: 4 variants x 128 rows x 128B = 64KB; 512 thr x 8 x 16B
    auto prefetch = [&](int chunk) {
        const int st = chunk % 3;
        const int k0 = chunk * 64;
#pragma unroll
        for (int w = 0; w < 4; w++) {
#pragma unroll
            for (int it = 0; it < 2; it++) {
                int p = tid + it * 512;            // 0..1023
                int r = p >> 3, cp = p & 7;
                const __nv_bfloat16* g =
                    srcs[w] + (size_t)(bases[w] + r) * GEMM_K + k0 + cp * 8;
                uint32_t d = sbase + (uint32_t)(st * G_STAGE + w * G_TILE
                                                + r * G_ROWB + cp * 16);
                CP_ASYNC16(d, g);
            }
        }
        CP_COMMIT();
    };

    prefetch(0);
    prefetch(1);

    const int NC = GEMM_K / 64;          // 16
    for (int c = 0; c < NC; c++) {
        if (c + 1 < NC) { CP_WAIT1(); } else { CP_WAIT0(); }
        __syncthreads();
        if (c + 2 < NC) prefetch(c + 2);   // overwrites stage (c-1)%3: safe

        const uint32_t bufBase = sbase + (uint32_t)((c % 3) * G_STAGE);
#pragma unroll
        for (int s = 0; s < 4; s++) {
            uint32_t ah[2][4], al[2][4], bh[2][4], bl[2][4];
            const int akb = s * 32 + ((lane >> 4) & 1) * 16;
            const int arow = wr * 32 + (lane & 7) + ((lane >> 3) & 1) * 8;
            ldm_x4(ah[0], bufBase + (uint32_t)(arow * G_ROWB + akb));
            ldm_x4(ah[1], bufBase + (uint32_t)((arow + 16) * G_ROWB + akb));
            ldm_x4(al[0], bufBase + (uint32_t)(G_TILE + arow * G_ROWB + akb));
            ldm_x4(al[1], bufBase + (uint32_t)(G_TILE + (arow + 16) * G_ROWB + akb));

            const int bkb = s * 32 + ((lane >> 3) & 1) * 16;
            const int brow = wc * 32 + ((lane >> 4) & 1) * 8 + (lane & 7);
#pragma unroll
            for (int p2 = 0; p2 < 2; p2++) {
                ldm_x4(bh[p2], bufBase + (uint32_t)(2 * G_TILE + (brow + p2 * 16) * G_ROWB + bkb));
                ldm_x4(bl[p2], bufBase + (uint32_t)(3 * G_TILE + (brow + p2 * 16) * G_ROWB + bkb));
            }

#pragma unroll
            for (int mt = 0; mt < 2; mt++)
#pragma unroll
                for (int nt = 0; nt < 4; nt++) {
                    const uint32_t* bhf = &bh[nt >> 1][(nt & 1) * 2];
                    const uint32_t* blf = &bl[nt >> 1][(nt & 1) * 2];
                    mma_bf16(acc[mt][nt], ah[mt], bhf);
                    mma_bf16(acc[mt][nt], ah[mt], blf);
                    mma_bf16(acc[mt][nt], al[mt], bhf);
                }
        }
    }

    const int r0 = lane >> 2;
    const int c0 = (lane & 3) * 2;
#pragma unroll
    for (int mt = 0; mt < 2; mt++) {
#pragma unroll
        for (int nt = 0; nt < 4; nt++) {
            const int n0 = colBase + wc * 32 + nt * 8 + c0;
            const float b0 = bias[n0], b1 = bias[n0 + 1];
#pragma unroll
            for (int half = 0; half < 2; half++) {
                const int m = rowBase + wr * 32 + mt * 16 + r0 + half * 8;
                float f0 = acc[mt][nt][half * 2 + 0] + b0;
                float f1 = acc[mt][nt][half * 2 + 1] + b1;
                if (mode == 0) {
                    const int bb = m >> 11, t = m & 2047;
                    const int sec = n0 >> 10, cc = n0 & 1023;
                    const int h = cc >> 6, d0 = cc & 63;
                    __nv_bfloat16* dh = (sec == 0 ? g_kh : sec == 1 ? g_qh : g_vh);
                    __nv_bfloat16* dl = (sec == 0 ? g_kl : sec == 1 ? g_ql : g_vl);
                    size_t off = (((size_t)(bb * 16 + h)) * T_SZ + t) * 64 + d0;
                    uint32_t hi = packbf(f0, f1);
                    uint32_t lo = packbf(f0 - lowf(hi), f1 - highf(hi));
                    *(uint32_t*)(dh + off) = hi;
                    *(uint32_t*)(dl + off) = lo;
                } else {
                    float2 v; v.x = f0; v.y = f1;
                    *(float2*)(out + (size_t)m * C_SZ + n0) = v;
                }
            }
        }
    }
}

// ---------------------------------------------------------------------------
// Flash attention, split-bf16 HMMA (unchanged; rel_err 9.4e-6).
// Source convention wei = K@Q^T: query-role = k-section, key-role = q-section.
// ---------------------------------------------------------------------------
#define AST   144
#define SQH_O 0
#define SQL_O (128 * AST)
#define SKV_O (2 * 128 * AST)
#define KVVAR (64 * AST)
#define KVBUF (4 * KVVAR)
#define ATT_SMEM (SKV_O + 2 * KVBUF)   // 110592

__global__ __launch_bounds__(256, 1)
void attn_hmma() {
    extern __shared__ char smem[];
    const uint32_t sbase = (uint32_t)__cvta_generic_to_shared(smem);
    const int tid = threadIdx.x;
    const int lane = tid & 31, w = tid >> 5;
    const int bh = blockIdx.x;
    const int it = (int)(gridDim.y - 1 - blockIdx.y);

    const size_t hb = (size_t)bh * T_SZ * 64;
    const __nv_bfloat16* roleQh = g_kh + hb;
    const __nv_bfloat16* roleQl = g_kl + hb;
    const __nv_bfloat16* kvsrc[4] = {g_qh + hb, g_ql + hb, g_vh + hb, g_vl + hb};

    auto prefetchKV = [&](int jt) {
        const int buf = jt & 1;
#pragma unroll
        for (int i = 0; i < 8; i++) {
            int p = tid + i * 256;
            int v = p >> 9, rem = p & 511;
            int r = rem >> 3, cp = rem & 7;
            const __nv_bfloat16* src = kvsrc[v] + (size_t)(jt * 64 + r) * 64 + cp * 8;
            uint32_t dst = sbase + (uint32_t)(SKV_O + buf * KVBUF + v * KVVAR
                                              + r * AST + cp * 16);
            CP_ASYNC16(dst, src);
        }
        CP_COMMIT();
    };

    prefetchKV(0);

    {
        const __nv_bfloat162 sc = __floats2bfloat162_rn(0.125f, 0.125f);
        for (int p = tid; p < 128 * 32; p += 256) {
            int r = p >> 5, c2 = p & 31;
            size_t go = (size_t)(it * 128 + r) * 64 + c2 * 2;
            __nv_bfloat162 vh = *(const __nv_bfloat162*)(roleQh + go);
            __nv_bfloat162 vl = *(const __nv_bfloat162*)(roleQl + go);
            *(__nv_bfloat162*)(smem + SQH_O + r * AST + c2 * 4) = __hmul2(vh, sc);
            *(__nv_bfloat162*)(smem + SQL_O + r * AST + c2 * 4) = __hmul2(vl, sc);
        }
    }
    __syncthreads();

    uint32_t ah[4][4], al[4][4];
    {
        const int arow = w * 16 + (lane & 7) + ((lane >> 3) & 1) * 8;
        const int ab = ((lane >> 4) & 1) * 16;
#pragma unroll
        for (int kk = 0; kk < 4; kk++) {
            ldm_x4(ah[kk], sbase + (uint32_t)(SQH_O + arow * AST + kk * 32 + ab));
            ldm_x4(al[kk], sbase + (uint32_t)(SQL_O + arow * AST + kk * 32 + ab));
        }
    }

    float m0 = -1e30f, m1 = -1e30f, l0 = 0.f, l1 = 0.f;
    float O[8][4];
#pragma unroll
    for (int dt = 0; dt < 8; dt++)
#pragma unroll
        for (int q = 0; q < 4; q++) O[dt][q] = 0.f;

    const int iwmin = it * 128 + w * 16;
    const int jlast = 2 * it + 1;

    for (int jt = 0; jt <= jlast; jt++) {
        CP_WAIT0();
        __syncthreads();
        if (jt < jlast) prefetchKV(jt + 1);

        if (jt * 64 <= iwmin + 15) {
            const uint32_t kb = sbase + (uint32_t)(SKV_O + (jt & 1) * KVBUF);
            float s[8][4];
#pragma unroll
            for (int nt = 0; nt < 8; nt++)
#pragma unroll
                for (int q = 0; q < 4; q++) s[nt][q] = 0.f;

#pragma unroll
            for (int kk = 0; kk < 4; kk++) {
                const int bb = kk * 32 + ((lane >> 3) & 1) * 16;
                const int br = ((lane >> 4) & 1) * 8 + (lane & 7);
#pragma unroll
                for (int np = 0; np < 4; np++) {
                    uint32_t kh4[4], kl4[4];
                    uint32_t a = kb + (uint32_t)((np * 16 + br) * AST + bb);
                    ldm_x4(kh4, a);
                    ldm_x4(kl4, a + KVVAR);
                    mma_bf16(s[2 * np],     ah[kk], kh4 + 0);
                    mma_bf16(s[2 * np],     ah[kk], kl4 + 0);
                    mma_bf16(s[2 * np],     al[kk], kh4 + 0);
                    mma_bf16(s[2 * np + 1], ah[kk], kh4 + 2);
                    mma_bf16(s[2 * np + 1], ah[kk], kl4 + 2);
                    mma_bf16(s[2 * np + 1], al[kk], kh4 + 2);
                }
            }

            const int i0 = iwmin + (lane >> 2);
            if (jt * 64 + 63 > iwmin) {
#pragma unroll
                for (int nt = 0; nt < 8; nt++)
#pragma unroll
                    for (int q = 0; q < 4; q++) {
                        int j = jt * 64 + nt * 8 + (lane & 3) * 2 + (q & 1);
                        int i = i0 + ((q >> 1) ? 8 : 0);
                        if (j > i) s[nt][q] = -1e30f;
                    }
            }

            float mx0 = -1e30f, mx1 = -1e30f;
#pragma unroll
            for (int nt = 0; nt < 8; nt++) {
                mx0 = fmaxf(mx0, fmaxf(s[nt][0], s[nt][1]));
                mx1 = fmaxf(mx1, fmaxf(s[nt][2], s[nt][3]));
            }
            mx0 = fmaxf(mx0, __shfl_xor_sync(0xffffffffu, mx0, 1));
            mx0 = fmaxf(mx0, __shfl_xor_sync(0xffffffffu, mx0, 2));
            mx1 = fmaxf(mx1, __shfl_xor_sync(0xffffffffu, mx1, 1));
            mx1 = fmaxf(mx1, __shfl_xor_sync(0xffffffffu, mx1, 2));
            float mn0 = fmaxf(m0, mx0), mn1 = fmaxf(m1, mx1);
            float a0 = __expf(m0 - mn0), a1 = __expf(m1 - mn1);
            float sum0 = 0.f, sum1 = 0.f;
#pragma unroll
            for (int nt = 0; nt < 8; nt++) {
                s[nt][0] = __expf(s[nt][0] - mn0);
                s[nt][1] = __expf(s[nt][1] - mn0);
                s[nt][2] = __expf(s[nt][2] - mn1);
                s[nt][3] = __expf(s[nt][3] - mn1);
                sum0 += s[nt][0] + s[nt][1];
                sum1 += s[nt][2] + s[nt][3];
            }
            sum0 += __shfl_xor_sync(0xffffffffu, sum0, 1);
            sum0 += __shfl_xor_sync(0xffffffffu, sum0, 2);
            sum1 += __shfl_xor_sync(0xffffffffu, sum1, 1);
            sum1 += __shfl_xor_sync(0xffffffffu, sum1, 2);
            l0 = l0 * a0 + sum0;  l1 = l1 * a1 + sum1;
            m0 = mn0;             m1 = mn1;
#pragma unroll
            for (int dt = 0; dt < 8; dt++) {
                O[dt][0] *= a0; O[dt][1] *= a0;
                O[dt][2] *= a1; O[dt][3] *= a1;
            }

#pragma unroll
            for (int kk = 0; kk < 4; kk++) {
                uint32_t pah[4], pal[4];
#pragma unroll
                for (int t = 0; t < 4; t++) {
                    float f0 = s[2 * kk + (t >> 1)][(t & 1) * 2 + 0];
                    float f1 = s[2 * kk + (t >> 1)][(t & 1) * 2 + 1];
                    pah[t] = packbf(f0, f1);
                    pal[t] = packbf(f0 - lowf(pah[t]), f1 - highf(pah[t]));
                }
                const int vrow = kk * 16 + (lane & 7) + ((lane >> 3) & 1) * 8;
                const int voff = ((lane >> 4) & 1) * 16;
#pragma unroll
                for (int dp = 0; dp < 4; dp++) {
                    uint32_t vh4[4], vl4[4];
                    uint32_t a = kb + (uint32_t)(2 * KVVAR + vrow * AST + dp * 32 + voff);
                    ldm_x4t(vh4, a);
                    ldm_x4t(vl4, a + KVVAR);
                    mma_bf16(O[2 * dp],     pah, vh4 + 0);
                    mma_bf16(O[2 * dp],     pal, vh4 + 0);
                    mma_bf16(O[2 * dp],     pah, vl4 + 0);
                    mma_bf16(O[2 * dp + 1], pah, vh4 + 2);
                    mma_bf16(O[2 * dp + 1], pal, vh4 + 2);
                    mma_bf16(O[2 * dp + 1], pah, vl4 + 2);
                }
            }
        }
    }

    const float inv0 = 1.f / l0, inv1 = 1.f / l1;
    const int b = bh >> 4, h = bh & 15;
    const int i0 = it * 128 + w * 16 + (lane >> 2);
#pragma unroll
    for (int dt = 0; dt < 8; dt++) {
        const int col = h * 64 + dt * 8 + (lane & 3) * 2;
        {
            float f0 = O[dt][0] * inv0, f1 = O[dt][1] * inv0;
            uint32_t hi = packbf(f0, f1);
            uint32_t lo = packbf(f0 - lowf(hi), f1 - highf(hi));
            size_t off = ((size_t)(b * T_SZ + i0)) * C_SZ + col;
            *(uint32_t*)(g_ao_hi + off) = hi;
            *(uint32_t*)(g_ao_lo + off) = lo;
        }
        {
            float f0 = O[dt][2] * inv1, f1 = O[dt][3] * inv1;
            uint32_t hi = packbf(f0, f1);
            uint32_t lo = packbf(f0 - lowf(hi), f1 - highf(hi));
            size_t off = ((size_t)(b * T_SZ + i0 + 8)) * C_SZ + col;
            *(uint32_t*)(g_ao_hi + off) = hi;
            *(uint32_t*)(g_ao_lo + off) = lo;
        }
    }
}

// ---------------------------------------------------------------------------
extern "C" void kernel_launch(void* const* d_in, const int* in_sizes, int n_in,
                              void* d_out, int out_size) {
    const float* x        = (const float*)d_in[0];
    const float* c_attn_w = (const float*)d_in[1];
    const float* c_attn_b = (const float*)d_in[2];
    const float* c_proj_w = (const float*)d_in[3];
    const float* c_proj_b = (const float*)d_in[4];
    float* out = (float*)d_out;

    split_x_kernel<<<(M_ROWS * C_SZ) / 256, 256>>>(x);
    tsplit_kernel<<<dim3(N_QKV / 32, GEMM_K / 32), dim3(32, 8)>>>(c_attn_w, N_QKV, 0);
    tsplit_kernel<<<dim3(C_SZ / 32, GEMM_K / 32), dim3(32, 8)>>>(c_proj_w, C_SZ, 1);

    cudaFuncSetAttribute(gemm_hmma,
                         cudaFuncAttributeMaxDynamicSharedMemorySize, GEMM_SMEM);
    cudaFuncSetAttribute(attn_hmma,
                         cudaFuncAttributeMaxDynamicSharedMemorySize, ATT_SMEM);

    gemm_hmma<<<dim3(N_QKV / 128, M_ROWS / 128), 512, GEMM_SMEM>>>(
        c_attn_b, nullptr, 0);

    attn_hmma<<<dim3(32, T_SZ / 128), 256, ATT_SMEM>>>();

    gemm_hmma<<<dim3(C_SZ / 128, M_ROWS / 128), 512, GEMM_SMEM>>>(
        c_proj_b, out, 1);
}

// round 8
// speedup vs baseline: 1.5507x; 1.5507x over previous
#include <cuda_runtime.h>
#include <cuda_bf16.h>
#include <cstdint>

#define B_SZ   2
#define T_SZ   2048
#define C_SZ   1024
#define M_ROWS 4096
#define N_QKV  3072
#define GEMM_K 1024

// ---------------------------------------------------------------------------
// Scratch (__device__ globals; no allocation allowed)
// ---------------------------------------------------------------------------
__device__ __nv_bfloat16 g_x_hi[M_ROWS * C_SZ];
__device__ __nv_bfloat16 g_x_lo[M_ROWS * C_SZ];
__device__ __nv_bfloat16 g_wq_hi[N_QKV * GEMM_K];   // transposed [n][k]
__device__ __nv_bfloat16 g_wq_lo[N_QKV * GEMM_K];
__device__ __nv_bfloat16 g_wp_hi[C_SZ * GEMM_K];    // transposed [n][k]
__device__ __nv_bfloat16 g_wp_lo[C_SZ * GEMM_K];
// qkv outputs, split bf16, [bh][t][d]
__device__ __nv_bfloat16 g_kh[32 * T_SZ * 64], g_kl[32 * T_SZ * 64];
__device__ __nv_bfloat16 g_qh[32 * T_SZ * 64], g_ql[32 * T_SZ * 64];
__device__ __nv_bfloat16 g_vh[32 * T_SZ * 64], g_vl[32 * T_SZ * 64];
// attention out, split bf16, [b][t][C]
__device__ __nv_bfloat16 g_ao_hi[M_ROWS * C_SZ], g_ao_lo[M_ROWS * C_SZ];

// ---------------------------------------------------------------------------
// PTX helpers (plain sm_103 target)
// ---------------------------------------------------------------------------
#define CP_ASYNC16(dst, src) \
    asm volatile("cp.async.cg.shared.global [%0], [%1], 16;" :: "r"(dst), "l"(src))
#define CP_COMMIT() asm volatile("cp.async.commit_group;" ::: "memory")
#define CP_WAIT0()  asm volatile("cp.async.wait_group 0;" ::: "memory")

__device__ __forceinline__ void ldm_x4(uint32_t* r, uint32_t a) {
    asm volatile("ldmatrix.sync.aligned.m8n8.x4.shared.b16 {%0,%1,%2,%3}, [%4];"
                 : "=r"(r[0]), "=r"(r[1]), "=r"(r[2]), "=r"(r[3]) : "r"(a));
}
__device__ __forceinline__ void ldm_x4t(uint32_t* r, uint32_t a) {
    asm volatile("ldmatrix.sync.aligned.m8n8.x4.trans.shared.b16 {%0,%1,%2,%3}, [%4];"
                 : "=r"(r[0]), "=r"(r[1]), "=r"(r[2]), "=r"(r[3]) : "r"(a));
}
__device__ __forceinline__ void mma_bf16(float* d, const uint32_t* a,
                                         const uint32_t* b) {
    asm volatile(
        "mma.sync.aligned.m16n8k16.row.col.f32.bf16.bf16.f32 "
        "{%0,%1,%2,%3}, {%4,%5,%6,%7}, {%8,%9}, {%0,%1,%2,%3};"
        : "+f"(d[0]), "+f"(d[1]), "+f"(d[2]), "+f"(d[3])
        : "r"(a[0]), "r"(a[1]), "r"(a[2]), "r"(a[3]), "r"(b[0]), "r"(b[1]));
}
__device__ __forceinline__ uint32_t packbf(float lo, float hi) {
    __nv_bfloat162 t = __floats2bfloat162_rn(lo, hi);
    return *reinterpret_cast<uint32_t*>(&t);
}
__device__ __forceinline__ float lowf(uint32_t u)  { return __uint_as_float(u << 16); }
__device__ __forceinline__ float highf(uint32_t u) { return __uint_as_float(u & 0xFFFF0000u); }

// ---------------------------------------------------------------------------
// Prep: fp32 -> (hi, lo) bf16
// ---------------------------------------------------------------------------
__global__ __launch_bounds__(256)
void split_x_kernel(const float* __restrict__ in) {
    int i = blockIdx.x * 256 + threadIdx.x;
    float v = in[i];
    __nv_bfloat16 h = __float2bfloat16(v);
    g_x_hi[i] = h;
    g_x_lo[i] = __float2bfloat16(v - __bfloat162float(h));
}

__global__ void tsplit_kernel(const float* __restrict__ w, int N, int mode) {
    __shared__ float tile[32][33];
    const int nb = blockIdx.x * 32, kb = blockIdx.y * 32;
    const int tx = threadIdx.x, ty = threadIdx.y;   // (32, 8)
#pragma unroll
    for (int i2 = 0; i2 < 32; i2 += 8)
        tile[ty + i2][tx] = w[(size_t)(kb + ty + i2) * N + nb + tx];
    __syncthreads();
    __nv_bfloat16* oh = mode ? g_wp_hi : g_wq_hi;
    __nv_bfloat16* ol = mode ? g_wp_lo : g_wq_lo;
#pragma unroll
    for (int i2 = 0; i2 < 32; i2 += 8) {
        float v = tile[tx][ty + i2];
        __nv_bfloat16 h = __float2bfloat16(v);
        size_t o = (size_t)(nb + ty + i2) * GEMM_K + kb + tx;
        oh[o] = h;
        ol[o] = __float2bfloat16(v - __bfloat162float(h));
    }
}

// ---------------------------------------------------------------------------
// HMMA split-bf16 GEMM, 128x64 tile, BK=64, 2-stage cp.async pipeline,
// 256 threads (8 warps, 4x2 grid, 32x32 per warp), 2 CTAs/SM (independent
// barriers -> desynchronized convoys keep the tensor pipe fed).
// mode 0: epilogue bias + split-write into g_{k,q,v}{h,l}  [bh][t][d]
// mode 1: epilogue bias + fp32 store to out
// ---------------------------------------------------------------------------
#define G_ROWB   144                       // 128B data + 16B pad
#define G_ATILE  (128 * G_ROWB)            // 18432 per A variant
#define G_BTILE  (64 * G_ROWB)             // 9216 per B variant
#define G_STAGE  (2 * G_ATILE + 2 * G_BTILE)  // 55296
#define GEMM_SMEM (2 * G_STAGE)            // 110592 -> 2 CTAs/SM

__global__ __launch_bounds__(256, 2)
void gemm_hmma(const float* __restrict__ bias, float* __restrict__ out,
               int mode) {
    extern __shared__ char smem[];
    const uint32_t sbase = (uint32_t)__cvta_generic_to_shared(smem);
    const int tid = threadIdx.x;
    const int lane = tid & 31, warp = tid >> 5;
    const int wr = warp & 3, wc = warp >> 2;      // 4x2 warp grid
    const int rowBase = blockIdx.y * 128;
    const int colBase = blockIdx.x * 64;

    const __nv_bfloat16 *aSrc[2], *bSrc[2];
    if (mode == 0) { aSrc[0] = g_x_hi;  aSrc[1] = g_x_lo;  bSrc[0] = g_wq_hi; bSrc[1] = g_wq_lo; }
    else           { aSrc[0] = g_ao_hi; aSrc[1] = g_ao_lo; bSrc[0] = g_wp_hi; bSrc[1] = g_wp_lo; }

    float acc[2][4][4];
#pragma unroll
    for (int mt = 0; mt < 2; mt++)
#pragma unroll
        for (int nt = 0; nt < 4; nt++)
#pragma unroll
            for (int q = 0; q < 4; q++) acc[mt][nt][q] = 0.f;

    // per chunk: A 2x128x128B = 32KB, B 2x64x128B = 16KB
    auto prefetch = [&](int chunk) {
        const int st = chunk & 1;
        const int k0 = chunk * 64;
#pragma unroll
        for (int v = 0; v < 2; v++) {
#pragma unroll
            for (int it = 0; it < 4; it++) {      // A: 1024 pieces
                int p = tid + it * 256;
                int r = p >> 3, cp = p & 7;
                const __nv_bfloat16* g =
                    aSrc[v] + (size_t)(rowBase + r) * GEMM_K + k0 + cp * 8;
                uint32_t d = sbase + (uint32_t)(st * G_STAGE + v * G_ATILE
                                                + r * G_ROWB + cp * 16);
                CP_ASYNC16(d, g);
            }
#pragma unroll
            for (int it = 0; it < 2; it++) {      // B: 512 pieces
                int p = tid + it * 256;
                int r = p >> 3, cp = p & 7;
                const __nv_bfloat16* g =
                    bSrc[v] + (size_t)(colBase + r) * GEMM_K + k0 + cp * 8;
                uint32_t d = sbase + (uint32_t)(st * G_STAGE + 2 * G_ATILE
                                                + v * G_BTILE + r * G_ROWB + cp * 16);
                CP_ASYNC16(d, g);
            }
        }
        CP_COMMIT();
    };

    prefetch(0);

    const int NC = GEMM_K / 64;          // 16
    for (int c = 0; c < NC; c++) {
        CP_WAIT0();
        __syncthreads();                  // all warps done with stage (c-1)&1
        if (c + 1 < NC) prefetch(c + 1);  // writes stage (c+1)&1 = (c-1)&1: safe

        const uint32_t bufBase = sbase + (uint32_t)((c & 1) * G_STAGE);
#pragma unroll
        for (int s = 0; s < 4; s++) {
            uint32_t ah[2][4], al[2][4], bh[2][4], bl[2][4];
            const int akb = s * 32 + ((lane >> 4) & 1) * 16;
            const int arow = wr * 32 + (lane & 7) + ((lane >> 3) & 1) * 8;
            ldm_x4(ah[0], bufBase + (uint32_t)(arow * G_ROWB + akb));
            ldm_x4(ah[1], bufBase + (uint32_t)((arow + 16) * G_ROWB + akb));
            ldm_x4(al[0], bufBase + (uint32_t)(G_ATILE + arow * G_ROWB + akb));
            ldm_x4(al[1], bufBase + (uint32_t)(G_ATILE + (arow + 16) * G_ROWB + akb));

            const int bkb = s * 32 + ((lane >> 3) & 1) * 16;
            const int brow = wc * 32 + ((lane >> 4) & 1) * 8 + (lane & 7);
#pragma unroll
            for (int p2 = 0; p2 < 2; p2++) {
                ldm_x4(bh[p2], bufBase + (uint32_t)(2 * G_ATILE + (brow + p2 * 16) * G_ROWB + bkb));
                ldm_x4(bl[p2], bufBase + (uint32_t)(2 * G_ATILE + G_BTILE + (brow + p2 * 16) * G_ROWB + bkb));
            }

#pragma unroll
            for (int mt = 0; mt < 2; mt++)
#pragma unroll
                for (int nt = 0; nt < 4; nt++) {
                    const uint32_t* bhf = &bh[nt >> 1][(nt & 1) * 2];
                    const uint32_t* blf = &bl[nt >> 1][(nt & 1) * 2];
                    mma_bf16(acc[mt][nt], ah[mt], bhf);
                    mma_bf16(acc[mt][nt], ah[mt], blf);
                    mma_bf16(acc[mt][nt], al[mt], bhf);
                }
        }
    }

    const int r0 = lane >> 2;
    const int c0 = (lane & 3) * 2;
#pragma unroll
    for (int mt = 0; mt < 2; mt++) {
#pragma unroll
        for (int nt = 0; nt < 4; nt++) {
            const int n0 = colBase + wc * 32 + nt * 8 + c0;
            const float b0 = bias[n0], b1 = bias[n0 + 1];
#pragma unroll
            for (int half = 0; half < 2; half++) {
                const int m = rowBase + wr * 32 + mt * 16 + r0 + half * 8;
                float f0 = acc[mt][nt][half * 2 + 0] + b0;
                float f1 = acc[mt][nt][half * 2 + 1] + b1;
                if (mode == 0) {
                    const int bb = m >> 11, t = m & 2047;
                    const int sec = n0 >> 10, cc = n0 & 1023;
                    const int h = cc >> 6, d0 = cc & 63;
                    __nv_bfloat16* dh = (sec == 0 ? g_kh : sec == 1 ? g_qh : g_vh);
                    __nv_bfloat16* dl = (sec == 0 ? g_kl : sec == 1 ? g_ql : g_vl);
                    size_t off = (((size_t)(bb * 16 + h)) * T_SZ + t) * 64 + d0;
                    uint32_t hi = packbf(f0, f1);
                    uint32_t lo = packbf(f0 - lowf(hi), f1 - highf(hi));
                    *(uint32_t*)(dh + off) = hi;
                    *(uint32_t*)(dl + off) = lo;
                } else {
                    float2 v; v.x = f0; v.y = f1;
                    *(float2*)(out + (size_t)m * C_SZ + n0) = v;
                }
            }
        }
    }
}

// ---------------------------------------------------------------------------
// Flash attention, split-bf16 HMMA (unchanged; rel_err 9.4e-6).
// Source convention wei = K@Q^T: query-role = k-section, key-role = q-section.
// ---------------------------------------------------------------------------
#define AST   144
#define SQH_O 0
#define SQL_O (128 * AST)
#define SKV_O (2 * 128 * AST)
#define KVVAR (64 * AST)
#define KVBUF (4 * KVVAR)
#define ATT_SMEM (SKV_O + 2 * KVBUF)   // 110592

__global__ __launch_bounds__(256, 1)
void attn_hmma() {
    extern __shared__ char smem[];
    const uint32_t sbase = (uint32_t)__cvta_generic_to_shared(smem);
    const int tid = threadIdx.x;
    const int lane = tid & 31, w = tid >> 5;
    const int bh = blockIdx.x;
    const int it = (int)(gridDim.y - 1 - blockIdx.y);

    const size_t hb = (size_t)bh * T_SZ * 64;
    const __nv_bfloat16* roleQh = g_kh + hb;
    const __nv_bfloat16* roleQl = g_kl + hb;
    const __nv_bfloat16* kvsrc[4] = {g_qh + hb, g_ql + hb, g_vh + hb, g_vl + hb};

    auto prefetchKV = [&](int jt) {
        const int buf = jt & 1;
#pragma unroll
        for (int i = 0; i < 8; i++) {
            int p = tid + i * 256;
            int v = p >> 9, rem = p & 511;
            int r = rem >> 3, cp = rem & 7;
            const __nv_bfloat16* src = kvsrc[v] + (size_t)(jt * 64 + r) * 64 + cp * 8;
            uint32_t dst = sbase + (uint32_t)(SKV_O + buf * KVBUF + v * KVVAR
                                              + r * AST + cp * 16);
            CP_ASYNC16(dst, src);
        }
        CP_COMMIT();
    };

    prefetchKV(0);

    {
        const __nv_bfloat162 sc = __floats2bfloat162_rn(0.125f, 0.125f);
        for (int p = tid; p < 128 * 32; p += 256) {
            int r = p >> 5, c2 = p & 31;
            size_t go = (size_t)(it * 128 + r) * 64 + c2 * 2;
            __nv_bfloat162 vh = *(const __nv_bfloat162*)(roleQh + go);
            __nv_bfloat162 vl = *(const __nv_bfloat162*)(roleQl + go);
            *(__nv_bfloat162*)(smem + SQH_O + r * AST + c2 * 4) = __hmul2(vh, sc);
            *(__nv_bfloat162*)(smem + SQL_O + r * AST + c2 * 4) = __hmul2(vl, sc);
        }
    }
    __syncthreads();

    uint32_t ah[4][4], al[4][4];
    {
        const int arow = w * 16 + (lane & 7) + ((lane >> 3) & 1) * 8;
        const int ab = ((lane >> 4) & 1) * 16;
#pragma unroll
        for (int kk = 0; kk < 4; kk++) {
            ldm_x4(ah[kk], sbase + (uint32_t)(SQH_O + arow * AST + kk * 32 + ab));
            ldm_x4(al[kk], sbase + (uint32_t)(SQL_O + arow * AST + kk * 32 + ab));
        }
    }

    float m0 = -1e30f, m1 = -1e30f, l0 = 0.f, l1 = 0.f;
    float O[8][4];
#pragma unroll
    for (int dt = 0; dt < 8; dt++)
#pragma unroll
        for (int q = 0; q < 4; q++) O[dt][q] = 0.f;

    const int iwmin = it * 128 + w * 16;
    const int jlast = 2 * it + 1;

    for (int jt = 0; jt <= jlast; jt++) {
        CP_WAIT0();
        __syncthreads();
        if (jt < jlast) prefetchKV(jt + 1);

        if (jt * 64 <= iwmin + 15) {
            const uint32_t kb = sbase + (uint32_t)(SKV_O + (jt & 1) * KVBUF);
            float s[8][4];
#pragma unroll
            for (int nt = 0; nt < 8; nt++)
#pragma unroll
                for (int q = 0; q < 4; q++) s[nt][q] = 0.f;

#pragma unroll
            for (int kk = 0; kk < 4; kk++) {
                const int bb = kk * 32 + ((lane >> 3) & 1) * 16;
                const int br = ((lane >> 4) & 1) * 8 + (lane & 7);
#pragma unroll
                for (int np = 0; np < 4; np++) {
                    uint32_t kh4[4], kl4[4];
                    uint32_t a = kb + (uint32_t)((np * 16 + br) * AST + bb);
                    ldm_x4(kh4, a);
                    ldm_x4(kl4, a + KVVAR);
                    mma_bf16(s[2 * np],     ah[kk], kh4 + 0);
                    mma_bf16(s[2 * np],     ah[kk], kl4 + 0);
                    mma_bf16(s[2 * np],     al[kk], kh4 + 0);
                    mma_bf16(s[2 * np + 1], ah[kk], kh4 + 2);
                    mma_bf16(s[2 * np + 1], ah[kk], kl4 + 2);
                    mma_bf16(s[2 * np + 1], al[kk], kh4 + 2);
                }
            }

            const int i0 = iwmin + (lane >> 2);
            if (jt * 64 + 63 > iwmin) {
#pragma unroll
                for (int nt = 0; nt < 8; nt++)
#pragma unroll
                    for (int q = 0; q < 4; q++) {
                        int j = jt * 64 + nt * 8 + (lane & 3) * 2 + (q & 1);
                        int i = i0 + ((q >> 1) ? 8 : 0);
                        if (j > i) s[nt][q] = -1e30f;
                    }
            }

            float mx0 = -1e30f, mx1 = -1e30f;
#pragma unroll
            for (int nt = 0; nt < 8; nt++) {
                mx0 = fmaxf(mx0, fmaxf(s[nt][0], s[nt][1]));
                mx1 = fmaxf(mx1, fmaxf(s[nt][2], s[nt][3]));
            }
            mx0 = fmaxf(mx0, __shfl_xor_sync(0xffffffffu, mx0, 1));
            mx0 = fmaxf(mx0, __shfl_xor_sync(0xffffffffu, mx0, 2));
            mx1 = fmaxf(mx1, __shfl_xor_sync(0xffffffffu, mx1, 1));
            mx1 = fmaxf(mx1, __shfl_xor_sync(0xffffffffu, mx1, 2));
            float mn0 = fmaxf(m0, mx0), mn1 = fmaxf(m1, mx1);
            float a0 = __expf(m0 - mn0), a1 = __expf(m1 - mn1);
            float sum0 = 0.f, sum1 = 0.f;
#pragma unroll
            for (int nt = 0; nt < 8; nt++) {
                s[nt][0] = __expf(s[nt][0] - mn0);
                s[nt][1] = __expf(s[nt][1] - mn0);
                s[nt][2] = __expf(s[nt][2] - mn1);
                s[nt][3] = __expf(s[nt][3] - mn1);
                sum0 += s[nt][0] + s[nt][1];
                sum1 += s[nt][2] + s[nt][3];
            }
            sum0 += __shfl_xor_sync(0xffffffffu, sum0, 1);
            sum0 += __shfl_xor_sync(0xffffffffu, sum0, 2);
            sum1 += __shfl_xor_sync(0xffffffffu, sum1, 1);
            sum1 += __shfl_xor_sync(0xffffffffu, sum1, 2);
            l0 = l0 * a0 + sum0;  l1 = l1 * a1 + sum1;
            m0 = mn0;             m1 = mn1;
#pragma unroll
            for (int dt = 0; dt < 8; dt++) {
                O[dt][0] *= a0; O[dt][1] *= a0;
                O[dt][2] *= a1; O[dt][3] *= a1;
            }

#pragma unroll
            for (int kk = 0; kk < 4; kk++) {
                uint32_t pah[4], pal[4];
#pragma unroll
                for (int t = 0; t < 4; t++) {
                    float f0 = s[2 * kk + (t >> 1)][(t & 1) * 2 + 0];
                    float f1 = s[2 * kk + (t >> 1)][(t & 1) * 2 + 1];
                    pah[t] = packbf(f0, f1);
                    pal[t] = packbf(f0 - lowf(pah[t]), f1 - highf(pah[t]));
                }
                const int vrow = kk * 16 + (lane & 7) + ((lane >> 3) & 1) * 8;
                const int voff = ((lane >> 4) & 1) * 16;
#pragma unroll
                for (int dp = 0; dp < 4; dp++) {
                    uint32_t vh4[4], vl4[4];
                    uint32_t a = kb + (uint32_t)(2 * KVVAR + vrow * AST + dp * 32 + voff);
                    ldm_x4t(vh4, a);
                    ldm_x4t(vl4, a + KVVAR);
                    mma_bf16(O[2 * dp],     pah, vh4 + 0);
                    mma_bf16(O[2 * dp],     pal, vh4 + 0);
                    mma_bf16(O[2 * dp],     pah, vl4 + 0);
                    mma_bf16(O[2 * dp + 1], pah, vh4 + 2);
                    mma_bf16(O[2 * dp + 1], pal, vh4 + 2);
                    mma_bf16(O[2 * dp + 1], pah, vl4 + 2);
                }
            }
        }
    }

    const float inv0 = 1.f / l0, inv1 = 1.f / l1;
    const int b = bh >> 4, h = bh & 15;
    const int i0 = it * 128 + w * 16 + (lane >> 2);
#pragma unroll
    for (int dt = 0; dt < 8; dt++) {
        const int col = h * 64 + dt * 8 + (lane & 3) * 2;
        {
            float f0 = O[dt][0] * inv0, f1 = O[dt][1] * inv0;
            uint32_t hi = packbf(f0, f1);
            uint32_t lo = packbf(f0 - lowf(hi), f1 - highf(hi));
            size_t off = ((size_t)(b * T_SZ + i0)) * C_SZ + col;
            *(uint32_t*)(g_ao_hi + off) = hi;
            *(uint32_t*)(g_ao_lo + off) = lo;
        }
        {
            float f0 = O[dt][2] * inv1, f1 = O[dt][3] * inv1;
            uint32_t hi = packbf(f0, f1);
            uint32_t lo = packbf(f0 - lowf(hi), f1 - highf(hi));
            size_t off = ((size_t)(b * T_SZ + i0 + 8)) * C_SZ + col;
            *(uint32_t*)(g_ao_hi + off) = hi;
            *(uint32_t*)(g_ao_lo + off) = lo;
        }
    }
}

// ---------------------------------------------------------------------------
extern "C" void kernel_launch(void* const* d_in, const int* in_sizes, int n_in,
                              void* d_out, int out_size) {
    const float* x        = (const float*)d_in[0];
    const float* c_attn_w = (const float*)d_in[1];
    const float* c_attn_b = (const float*)d_in[2];
    const float* c_proj_w = (const float*)d_in[3];
    const float* c_proj_b = (const float*)d_in[4];
    float* out = (float*)d_out;

    split_x_kernel<<<(M_ROWS * C_SZ) / 256, 256>>>(x);
    tsplit_kernel<<<dim3(N_QKV / 32, GEMM_K / 32), dim3(32, 8)>>>(c_attn_w, N_QKV, 0);
    tsplit_kernel<<<dim3(C_SZ / 32, GEMM_K / 32), dim3(32, 8)>>>(c_proj_w, C_SZ, 1);

    cudaFuncSetAttribute(gemm_hmma,
                         cudaFuncAttributeMaxDynamicSharedMemorySize, GEMM_SMEM);
    cudaFuncSetAttribute(attn_hmma,
                         cudaFuncAttributeMaxDynamicSharedMemorySize, ATT_SMEM);

    gemm_hmma<<<dim3(N_QKV / 64, M_ROWS / 128), 256, GEMM_SMEM>>>(
        c_attn_b, nullptr, 0);

    attn_hmma<<<dim3(32, T_SZ / 128), 256, ATT_SMEM>>>();

    gemm_hmma<<<dim3(C_SZ / 64, M_ROWS / 128), 256, GEMM_SMEM>>>(
        c_proj_b, out, 1);
}

// round 9
// speedup vs baseline: 1.6968x; 1.0942x over previous
#include <cuda_runtime.h>
#include <cuda_bf16.h>
#include <cstdint>

#define B_SZ   2
#define T_SZ   2048
#define C_SZ   1024
#define M_ROWS 4096
#define N_QKV  3072
#define GEMM_K 1024

// ---------------------------------------------------------------------------
// Scratch (__device__ globals; no allocation allowed)
// ---------------------------------------------------------------------------
__device__ __nv_bfloat16 g_x_hi[M_ROWS * C_SZ];
__device__ __nv_bfloat16 g_x_lo[M_ROWS * C_SZ];
__device__ __nv_bfloat16 g_wq_hi[N_QKV * GEMM_K];   // transposed [n][k]
__device__ __nv_bfloat16 g_wq_lo[N_QKV * GEMM_K];
__device__ __nv_bfloat16 g_wp_hi[C_SZ * GEMM_K];    // transposed [n][k]
__device__ __nv_bfloat16 g_wp_lo[C_SZ * GEMM_K];
// qkv outputs, split bf16, [bh][t][d]
__device__ __nv_bfloat16 g_kh[32 * T_SZ * 64], g_kl[32 * T_SZ * 64];
__device__ __nv_bfloat16 g_qh[32 * T_SZ * 64], g_ql[32 * T_SZ * 64];
__device__ __nv_bfloat16 g_vh[32 * T_SZ * 64], g_vl[32 * T_SZ * 64];
// attention out, split bf16, [b][t][C]
__device__ __nv_bfloat16 g_ao_hi[M_ROWS * C_SZ], g_ao_lo[M_ROWS * C_SZ];

// ---------------------------------------------------------------------------
// PTX helpers (plain sm_103 target)
// ---------------------------------------------------------------------------
#define CP_ASYNC16(dst, src) \
    asm volatile("cp.async.cg.shared.global [%0], [%1], 16;" :: "r"(dst), "l"(src))
#define CP_COMMIT() asm volatile("cp.async.commit_group;" ::: "memory")
#define CP_WAIT0()  asm volatile("cp.async.wait_group 0;" ::: "memory")

__device__ __forceinline__ void ldm_x4(uint32_t* r, uint32_t a) {
    asm volatile("ldmatrix.sync.aligned.m8n8.x4.shared.b16 {%0,%1,%2,%3}, [%4];"
                 : "=r"(r[0]), "=r"(r[1]), "=r"(r[2]), "=r"(r[3]) : "r"(a));
}
__device__ __forceinline__ void ldm_x4t(uint32_t* r, uint32_t a) {
    asm volatile("ldmatrix.sync.aligned.m8n8.x4.trans.shared.b16 {%0,%1,%2,%3}, [%4];"
                 : "=r"(r[0]), "=r"(r[1]), "=r"(r[2]), "=r"(r[3]) : "r"(a));
}
__device__ __forceinline__ void mma_bf16(float* d, const uint32_t* a,
                                         const uint32_t* b) {
    asm volatile(
        "mma.sync.aligned.m16n8k16.row.col.f32.bf16.bf16.f32 "
        "{%0,%1,%2,%3}, {%4,%5,%6,%7}, {%8,%9}, {%0,%1,%2,%3};"
        : "+f"(d[0]), "+f"(d[1]), "+f"(d[2]), "+f"(d[3])
        : "r"(a[0]), "r"(a[1]), "r"(a[2]), "r"(a[3]), "r"(b[0]), "r"(b[1]));
}
__device__ __forceinline__ uint32_t packbf(float lo, float hi) {
    __nv_bfloat162 t = __floats2bfloat162_rn(lo, hi);
    return *reinterpret_cast<uint32_t*>(&t);
}
__device__ __forceinline__ float lowf(uint32_t u)  { return __uint_as_float(u << 16); }
__device__ __forceinline__ float highf(uint32_t u) { return __uint_as_float(u & 0xFFFF0000u); }

// ---------------------------------------------------------------------------
// Fused prep kernel: one launch for x-split + both weight transpose-splits.
// blocks [0, 16384)            : split x       (256 thr 1D)
// blocks [16384, 16384+3072)   : tsplit wq     (treated as (32,8))
// blocks [19456, 19456+1024)   : tsplit wp
// ---------------------------------------------------------------------------
__global__ __launch_bounds__(256)
void prep_kernel(const float* __restrict__ x,
                 const float* __restrict__ wq,
                 const float* __restrict__ wp) {
    __shared__ float tile[32][33];
    const int blk = blockIdx.x;
    const int tid = threadIdx.x;

    if (blk < 16384) {
        int i = blk * 256 + tid;
        float v = x[i];
        __nv_bfloat16 h = __float2bfloat16(v);
        g_x_hi[i] = h;
        g_x_lo[i] = __float2bfloat16(v - __bfloat162float(h));
        return;
    }

    const float* w;
    __nv_bfloat16 *oh, *ol;
    int N, bb;
    if (blk < 16384 + 3072) {
        bb = blk - 16384; w = wq; oh = g_wq_hi; ol = g_wq_lo; N = N_QKV;
    } else {
        bb = blk - 19456; w = wp; oh = g_wp_hi; ol = g_wp_lo; N = C_SZ;
    }
    const int nb = (bb % (N / 32)) * 32;
    const int kb = (bb / (N / 32)) * 32;
    const int tx = tid & 31, ty = tid >> 5;
#pragma unroll
    for (int i2 = 0; i2 < 32; i2 += 8)
        tile[ty + i2][tx] = w[(size_t)(kb + ty + i2) * N + nb + tx];
    __syncthreads();
#pragma unroll
    for (int i2 = 0; i2 < 32; i2 += 8) {
        float v = tile[tx][ty + i2];
        __nv_bfloat16 h = __float2bfloat16(v);
        size_t o = (size_t)(nb + ty + i2) * GEMM_K + kb + tx;
        oh[o] = h;
        ol[o] = __float2bfloat16(v - __bfloat162float(h));
    }
}

// ---------------------------------------------------------------------------
// HMMA split-bf16 GEMM (round-8 config: 128x64 tile, BK=64, 2-stage,
// 256 threads 4x2 warps, 2 CTAs/SM).
// ---------------------------------------------------------------------------
#define G_ROWB   144
#define G_ATILE  (128 * G_ROWB)
#define G_BTILE  (64 * G_ROWB)
#define G_STAGE  (2 * G_ATILE + 2 * G_BTILE)  // 55296
#define GEMM_SMEM (2 * G_STAGE)               // 110592

__global__ __launch_bounds__(256, 2)
void gemm_hmma(const float* __restrict__ bias, float* __restrict__ out,
               int mode) {
    extern __shared__ char smem[];
    const uint32_t sbase = (uint32_t)__cvta_generic_to_shared(smem);
    const int tid = threadIdx.x;
    const int lane = tid & 31, warp = tid >> 5;
    const int wr = warp & 3, wc = warp >> 2;
    const int rowBase = blockIdx.y * 128;
    const int colBase = blockIdx.x * 64;

    const __nv_bfloat16 *aSrc[2], *bSrc[2];
    if (mode == 0) { aSrc[0] = g_x_hi;  aSrc[1] = g_x_lo;  bSrc[0] = g_wq_hi; bSrc[1] = g_wq_lo; }
    else           { aSrc[0] = g_ao_hi; aSrc[1] = g_ao_lo; bSrc[0] = g_wp_hi; bSrc[1] = g_wp_lo; }

    float acc[2][4][4];
#pragma unroll
    for (int mt = 0; mt < 2; mt++)
#pragma unroll
        for (int nt = 0; nt < 4; nt++)
#pragma unroll
            for (int q = 0; q < 4; q++) acc[mt][nt][q] = 0.f;

    auto prefetch = [&](int chunk) {
        const int st = chunk & 1;
        const int k0 = chunk * 64;
#pragma unroll
        for (int v = 0; v < 2; v++) {
#pragma unroll
            for (int it = 0; it < 4; it++) {
                int p = tid + it * 256;
                int r = p >> 3, cp = p & 7;
                const __nv_bfloat16* g =
                    aSrc[v] + (size_t)(rowBase + r) * GEMM_K + k0 + cp * 8;
                uint32_t d = sbase + (uint32_t)(st * G_STAGE + v * G_ATILE
                                                + r * G_ROWB + cp * 16);
                CP_ASYNC16(d, g);
            }
#pragma unroll
            for (int it = 0; it < 2; it++) {
                int p = tid + it * 256;
                int r = p >> 3, cp = p & 7;
                const __nv_bfloat16* g =
                    bSrc[v] + (size_t)(colBase + r) * GEMM_K + k0 + cp * 8;
                uint32_t d = sbase + (uint32_t)(st * G_STAGE + 2 * G_ATILE
                                                + v * G_BTILE + r * G_ROWB + cp * 16);
                CP_ASYNC16(d, g);
            }
        }
        CP_COMMIT();
    };

    prefetch(0);

    const int NC = GEMM_K / 64;
    for (int c = 0; c < NC; c++) {
        CP_WAIT0();
        __syncthreads();
        if (c + 1 < NC) prefetch(c + 1);

        const uint32_t bufBase = sbase + (uint32_t)((c & 1) * G_STAGE);
#pragma unroll
        for (int s = 0; s < 4; s++) {
            uint32_t ah[2][4], al[2][4], bh[2][4], bl[2][4];
            const int akb = s * 32 + ((lane >> 4) & 1) * 16;
            const int arow = wr * 32 + (lane & 7) + ((lane >> 3) & 1) * 8;
            ldm_x4(ah[0], bufBase + (uint32_t)(arow * G_ROWB + akb));
            ldm_x4(ah[1], bufBase + (uint32_t)((arow + 16) * G_ROWB + akb));
            ldm_x4(al[0], bufBase + (uint32_t)(G_ATILE + arow * G_ROWB + akb));
            ldm_x4(al[1], bufBase + (uint32_t)(G_ATILE + (arow + 16) * G_ROWB + akb));

            const int bkb = s * 32 + ((lane >> 3) & 1) * 16;
            const int brow = wc * 32 + ((lane >> 4) & 1) * 8 + (lane & 7);
#pragma unroll
            for (int p2 = 0; p2 < 2; p2++) {
                ldm_x4(bh[p2], bufBase + (uint32_t)(2 * G_ATILE + (brow + p2 * 16) * G_ROWB + bkb));
                ldm_x4(bl[p2], bufBase + (uint32_t)(2 * G_ATILE + G_BTILE + (brow + p2 * 16) * G_ROWB + bkb));
            }

#pragma unroll
            for (int mt = 0; mt < 2; mt++)
#pragma unroll
                for (int nt = 0; nt < 4; nt++) {
                    const uint32_t* bhf = &bh[nt >> 1][(nt & 1) * 2];
                    const uint32_t* blf = &bl[nt >> 1][(nt & 1) * 2];
                    mma_bf16(acc[mt][nt], ah[mt], bhf);
                    mma_bf16(acc[mt][nt], ah[mt], blf);
                    mma_bf16(acc[mt][nt], al[mt], bhf);
                }
        }
    }

    const int r0 = lane >> 2;
    const int c0 = (lane & 3) * 2;
#pragma unroll
    for (int mt = 0; mt < 2; mt++) {
#pragma unroll
        for (int nt = 0; nt < 4; nt++) {
            const int n0 = colBase + wc * 32 + nt * 8 + c0;
            const float b0 = bias[n0], b1 = bias[n0 + 1];
#pragma unroll
            for (int half = 0; half < 2; half++) {
                const int m = rowBase + wr * 32 + mt * 16 + r0 + half * 8;
                float f0 = acc[mt][nt][half * 2 + 0] + b0;
                float f1 = acc[mt][nt][half * 2 + 1] + b1;
                if (mode == 0) {
                    const int bb = m >> 11, t = m & 2047;
                    const int sec = n0 >> 10, cc = n0 & 1023;
                    const int h = cc >> 6, d0 = cc & 63;
                    __nv_bfloat16* dh = (sec == 0 ? g_kh : sec == 1 ? g_qh : g_vh);
                    __nv_bfloat16* dl = (sec == 0 ? g_kl : sec == 1 ? g_ql : g_vl);
                    size_t off = (((size_t)(bb * 16 + h)) * T_SZ + t) * 64 + d0;
                    uint32_t hi = packbf(f0, f1);
                    uint32_t lo = packbf(f0 - lowf(hi), f1 - highf(hi));
                    *(uint32_t*)(dh + off) = hi;
                    *(uint32_t*)(dl + off) = lo;
                } else {
                    float2 v; v.x = f0; v.y = f1;
                    *(float2*)(out + (size_t)m * C_SZ + n0) = v;
                }
            }
        }
    }
}

// ---------------------------------------------------------------------------
// Flash attention v3: 256-row i-tiles (8 warps x 32 rows). K/V fragment LDS
// is amortized over 2x the rows -> tensor-bound instead of crossbar-bound.
// Source convention wei = K@Q^T: query-role = k-section, key-role = q-section.
// ---------------------------------------------------------------------------
#define AST   144
#define SQH_O 0
#define SQL_O (256 * AST)              // 36864
#define SKV_O (2 * 256 * AST)          // 73728
#define KVVAR (64 * AST)               // 9216
#define KVBUF (4 * KVVAR)              // 36864
#define ATT_SMEM (SKV_O + 2 * KVBUF)   // 147456

__global__ __launch_bounds__(256, 1)
void attn_hmma() {
    extern __shared__ char smem[];
    const uint32_t sbase = (uint32_t)__cvta_generic_to_shared(smem);
    const int tid = threadIdx.x;
    const int lane = tid & 31, w = tid >> 5;
    const int bh = blockIdx.x;
    const int it = (int)(gridDim.y - 1 - blockIdx.y);   // heavy blocks first

    const size_t hb = (size_t)bh * T_SZ * 64;
    const __nv_bfloat16* roleQh = g_kh + hb;            // query-role = k
    const __nv_bfloat16* roleQl = g_kl + hb;
    const __nv_bfloat16* kvsrc[4] = {g_qh + hb, g_ql + hb, g_vh + hb, g_vl + hb};

    auto prefetchKV = [&](int jt) {
        const int buf = jt & 1;
#pragma unroll
        for (int i = 0; i < 8; i++) {
            int p = tid + i * 256;
            int v = p >> 9, rem = p & 511;
            int r = rem >> 3, cp = rem & 7;
            const __nv_bfloat16* src = kvsrc[v] + (size_t)(jt * 64 + r) * 64 + cp * 8;
            uint32_t dst = sbase + (uint32_t)(SKV_O + buf * KVBUF + v * KVVAR
                                              + r * AST + cp * 16);
            CP_ASYNC16(dst, src);
        }
        CP_COMMIT();
    };

    prefetchKV(0);

    // Q tile: 256 rows, scaled by 1/8 (exact in bf16)
    {
        const __nv_bfloat162 sc = __floats2bfloat162_rn(0.125f, 0.125f);
        for (int p = tid; p < 256 * 32; p += 256) {
            int r = p >> 5, c2 = p & 31;
            size_t go = (size_t)(it * 256 + r) * 64 + c2 * 2;
            __nv_bfloat162 vh = *(const __nv_bfloat162*)(roleQh + go);
            __nv_bfloat162 vl = *(const __nv_bfloat162*)(roleQl + go);
            *(__nv_bfloat162*)(smem + SQH_O + r * AST + c2 * 4) = __hmul2(vh, sc);
            *(__nv_bfloat162*)(smem + SQL_O + r * AST + c2 * 4) = __hmul2(vl, sc);
        }
    }
    __syncthreads();

    float m[2][2], l[2][2];
#pragma unroll
    for (int mt = 0; mt < 2; mt++) { m[mt][0] = m[mt][1] = -1e30f; l[mt][0] = l[mt][1] = 0.f; }
    float O[2][8][4];
#pragma unroll
    for (int mt = 0; mt < 2; mt++)
#pragma unroll
        for (int dt = 0; dt < 8; dt++)
#pragma unroll
            for (int q = 0; q < 4; q++) O[mt][dt][q] = 0.f;

    const int iw = it * 256 + w * 32;        // warp's first row
    const int jlast = 4 * it + 3;

    for (int jt = 0; jt <= jlast; jt++) {
        CP_WAIT0();
        __syncthreads();
        if (jt < jlast) prefetchKV(jt + 1);

        if (jt * 64 <= iw + 31) {            // warp has unmasked work
            const uint32_t kb = sbase + (uint32_t)(SKV_O + (jt & 1) * KVBUF);
            float s[2][8][4];
#pragma unroll
            for (int mt = 0; mt < 2; mt++)
#pragma unroll
                for (int nt = 0; nt < 8; nt++)
#pragma unroll
                    for (int q = 0; q < 4; q++) s[mt][nt][q] = 0.f;

            // ---- scores: S = Qs @ K^T (3-pass split) ----
#pragma unroll
            for (int kk = 0; kk < 4; kk++) {
                uint32_t qh[2][4], ql[2][4];
                const int ab = kk * 32 + ((lane >> 4) & 1) * 16;
                const int arow = w * 32 + (lane & 7) + ((lane >> 3) & 1) * 8;
                ldm_x4(qh[0], sbase + (uint32_t)(SQH_O + arow * AST + ab));
                ldm_x4(qh[1], sbase + (uint32_t)(SQH_O + (arow + 16) * AST + ab));
                ldm_x4(ql[0], sbase + (uint32_t)(SQL_O + arow * AST + ab));
                ldm_x4(ql[1], sbase + (uint32_t)(SQL_O + (arow + 16) * AST + ab));

                const int bb = kk * 32 + ((lane >> 3) & 1) * 16;
                const int br = ((lane >> 4) & 1) * 8 + (lane & 7);
#pragma unroll
                for (int np = 0; np < 4; np++) {
                    uint32_t kh4[4], kl4[4];
                    uint32_t a = kb + (uint32_t)((np * 16 + br) * AST + bb);
                    ldm_x4(kh4, a);
                    ldm_x4(kl4, a + KVVAR);
#pragma unroll
                    for (int mt = 0; mt < 2; mt++) {
                        mma_bf16(s[mt][2 * np],     qh[mt], kh4 + 0);
                        mma_bf16(s[mt][2 * np],     qh[mt], kl4 + 0);
                        mma_bf16(s[mt][2 * np],     ql[mt], kh4 + 0);
                        mma_bf16(s[mt][2 * np + 1], qh[mt], kh4 + 2);
                        mma_bf16(s[mt][2 * np + 1], qh[mt], kl4 + 2);
                        mma_bf16(s[mt][2 * np + 1], ql[mt], kh4 + 2);
                    }
                }
            }

            // ---- causal mask ----
            const int i0 = iw + (lane >> 2);
            if (jt * 64 + 63 > iw) {
#pragma unroll
                for (int mt = 0; mt < 2; mt++)
#pragma unroll
                    for (int nt = 0; nt < 8; nt++)
#pragma unroll
                        for (int q = 0; q < 4; q++) {
                            int j = jt * 64 + nt * 8 + (lane & 3) * 2 + (q & 1);
                            int i = i0 + mt * 16 + ((q >> 1) ? 8 : 0);
                            if (j > i) s[mt][nt][q] = -1e30f;
                        }
            }

            // ---- online softmax (per mt, per row-half) ----
#pragma unroll
            for (int mt = 0; mt < 2; mt++) {
                float mx0 = -1e30f, mx1 = -1e30f;
#pragma unroll
                for (int nt = 0; nt < 8; nt++) {
                    mx0 = fmaxf(mx0, fmaxf(s[mt][nt][0], s[mt][nt][1]));
                    mx1 = fmaxf(mx1, fmaxf(s[mt][nt][2], s[mt][nt][3]));
                }
                mx0 = fmaxf(mx0, __shfl_xor_sync(0xffffffffu, mx0, 1));
                mx0 = fmaxf(mx0, __shfl_xor_sync(0xffffffffu, mx0, 2));
                mx1 = fmaxf(mx1, __shfl_xor_sync(0xffffffffu, mx1, 1));
                mx1 = fmaxf(mx1, __shfl_xor_sync(0xffffffffu, mx1, 2));
                float mn0 = fmaxf(m[mt][0], mx0), mn1 = fmaxf(m[mt][1], mx1);
                float a0 = __expf(m[mt][0] - mn0), a1 = __expf(m[mt][1] - mn1);
                float sum0 = 0.f, sum1 = 0.f;
#pragma unroll
                for (int nt = 0; nt < 8; nt++) {
                    s[mt][nt][0] = __expf(s[mt][nt][0] - mn0);
                    s[mt][nt][1] = __expf(s[mt][nt][1] - mn0);
                    s[mt][nt][2] = __expf(s[mt][nt][2] - mn1);
                    s[mt][nt][3] = __expf(s[mt][nt][3] - mn1);
                    sum0 += s[mt][nt][0] + s[mt][nt][1];
                    sum1 += s[mt][nt][2] + s[mt][nt][3];
                }
                sum0 += __shfl_xor_sync(0xffffffffu, sum0, 1);
                sum0 += __shfl_xor_sync(0xffffffffu, sum0, 2);
                sum1 += __shfl_xor_sync(0xffffffffu, sum1, 1);
                sum1 += __shfl_xor_sync(0xffffffffu, sum1, 2);
                l[mt][0] = l[mt][0] * a0 + sum0;
                l[mt][1] = l[mt][1] * a1 + sum1;
                m[mt][0] = mn0;  m[mt][1] = mn1;
#pragma unroll
                for (int dt = 0; dt < 8; dt++) {
                    O[mt][dt][0] *= a0; O[mt][dt][1] *= a0;
                    O[mt][dt][2] *= a1; O[mt][dt][3] *= a1;
                }
            }

            // ---- PV: O += P @ V (3-pass split, P from fragment regs) ----
#pragma unroll
            for (int kk = 0; kk < 4; kk++) {
                uint32_t pah[2][4], pal[2][4];
#pragma unroll
                for (int mt = 0; mt < 2; mt++)
#pragma unroll
                    for (int t = 0; t < 4; t++) {
                        float f0 = s[mt][2 * kk + (t >> 1)][(t & 1) * 2 + 0];
                        float f1 = s[mt][2 * kk + (t >> 1)][(t & 1) * 2 + 1];
                        pah[mt][t] = packbf(f0, f1);
                        pal[mt][t] = packbf(f0 - lowf(pah[mt][t]), f1 - highf(pah[mt][t]));
                    }
                const int vrow = kk * 16 + (lane & 7) + ((lane >> 3) & 1) * 8;
                const int voff = ((lane >> 4) & 1) * 16;
#pragma unroll
                for (int dp = 0; dp < 4; dp++) {
                    uint32_t vh4[4], vl4[4];
                    uint32_t a = kb + (uint32_t)(2 * KVVAR + vrow * AST + dp * 32 + voff);
                    ldm_x4t(vh4, a);
                    ldm_x4t(vl4, a + KVVAR);
#pragma unroll
                    for (int mt = 0; mt < 2; mt++) {
                        mma_bf16(O[mt][2 * dp],     pah[mt], vh4 + 0);
                        mma_bf16(O[mt][2 * dp],     pal[mt], vh4 + 0);
                        mma_bf16(O[mt][2 * dp],     pah[mt], vl4 + 0);
                        mma_bf16(O[mt][2 * dp + 1], pah[mt], vh4 + 2);
                        mma_bf16(O[mt][2 * dp + 1], pal[mt], vh4 + 2);
                        mma_bf16(O[mt][2 * dp + 1], pah[mt], vl4 + 2);
                    }
                }
            }
        }
    }

    // ---- epilogue: normalize, split to bf16, write [b][t][C] ----
    const int b = bh >> 4, h = bh & 15;
#pragma unroll
    for (int mt = 0; mt < 2; mt++) {
        const float inv0 = 1.f / l[mt][0], inv1 = 1.f / l[mt][1];
        const int i0 = iw + mt * 16 + (lane >> 2);
#pragma unroll
        for (int dt = 0; dt < 8; dt++) {
            const int col = h * 64 + dt * 8 + (lane & 3) * 2;
            {
                float f0 = O[mt][dt][0] * inv0, f1 = O[mt][dt][1] * inv0;
                uint32_t hi = packbf(f0, f1);
                uint32_t lo = packbf(f0 - lowf(hi), f1 - highf(hi));
                size_t off = ((size_t)(b * T_SZ + i0)) * C_SZ + col;
                *(uint32_t*)(g_ao_hi + off) = hi;
                *(uint32_t*)(g_ao_lo + off) = lo;
            }
            {
                float f0 = O[mt][dt][2] * inv1, f1 = O[mt][dt][3] * inv1;
                uint32_t hi = packbf(f0, f1);
                uint32_t lo = packbf(f0 - lowf(hi), f1 - highf(hi));
                size_t off = ((size_t)(b * T_SZ + i0 + 8)) * C_SZ + col;
                *(uint32_t*)(g_ao_hi + off) = hi;
                *(uint32_t*)(g_ao_lo + off) = lo;
            }
        }
    }
}

// ---------------------------------------------------------------------------
extern "C" void kernel_launch(void* const* d_in, const int* in_sizes, int n_in,
                              void* d_out, int out_size) {
    const float* x        = (const float*)d_in[0];
    const float* c_attn_w = (const float*)d_in[1];
    const float* c_attn_b = (const float*)d_in[2];
    const float* c_proj_w = (const float*)d_in[3];
    const float* c_proj_b = (const float*)d_in[4];
    float* out = (float*)d_out;

    prep_kernel<<<16384 + 3072 + 1024, 256>>>(x, c_attn_w, c_proj_w);

    cudaFuncSetAttribute(gemm_hmma,
                         cudaFuncAttributeMaxDynamicSharedMemorySize, GEMM_SMEM);
    cudaFuncSetAttribute(attn_hmma,
                         cudaFuncAttributeMaxDynamicSharedMemorySize, ATT_SMEM);

    gemm_hmma<<<dim3(N_QKV / 64, M_ROWS / 128), 256, GEMM_SMEM>>>(
        c_attn_b, nullptr, 0);

    attn_hmma<<<dim3(32, T_SZ / 256), 256, ATT_SMEM>>>();

    gemm_hmma<<<dim3(C_SZ / 64, M_ROWS / 128), 256, GEMM_SMEM>>>(
        c_proj_b, out, 1);
}

// round 10
// speedup vs baseline: 1.8754x; 1.1052x over previous
#include <cuda_runtime.h>
#include <cuda_bf16.h>
#include <cuda_fp16.h>
#include <cstdint>

#define B_SZ   2
#define T_SZ   2048
#define C_SZ   1024
#define M_ROWS 4096
#define N_QKV  3072
#define GEMM_K 1024

// ---------------------------------------------------------------------------
// Scratch (__device__ globals; no allocation allowed)
// ---------------------------------------------------------------------------
__device__ __nv_bfloat16 g_x_hi[M_ROWS * C_SZ];
__device__ __nv_bfloat16 g_x_lo[M_ROWS * C_SZ];
__device__ __nv_bfloat16 g_wq_hi[N_QKV * GEMM_K];
__device__ __nv_bfloat16 g_wq_lo[N_QKV * GEMM_K];
__device__ __nv_bfloat16 g_wp_hi[C_SZ * GEMM_K];
__device__ __nv_bfloat16 g_wp_lo[C_SZ * GEMM_K];
// qkv for attention, fp16: k split (query-role, exact), q hi-only (pre-scaled
// by 0.125), v split. [bh][t][d]
__device__ __half g_k16h[32 * T_SZ * 64], g_k16l[32 * T_SZ * 64];
__device__ __half g_q16h[32 * T_SZ * 64];
__device__ __half g_v16h[32 * T_SZ * 64], g_v16l[32 * T_SZ * 64];
// attention out, split bf16 (proj stays 3-pass bf16), [b][t][C]
__device__ __nv_bfloat16 g_ao_hi[M_ROWS * C_SZ], g_ao_lo[M_ROWS * C_SZ];

// ---------------------------------------------------------------------------
// PTX helpers (plain sm_103 target)
// ---------------------------------------------------------------------------
#define CP_ASYNC16(dst, src) \
    asm volatile("cp.async.cg.shared.global [%0], [%1], 16;" :: "r"(dst), "l"(src))
#define CP_COMMIT() asm volatile("cp.async.commit_group;" ::: "memory")
#define CP_WAIT0()  asm volatile("cp.async.wait_group 0;" ::: "memory")

__device__ __forceinline__ void ldm_x4(uint32_t* r, uint32_t a) {
    asm volatile("ldmatrix.sync.aligned.m8n8.x4.shared.b16 {%0,%1,%2,%3}, [%4];"
                 : "=r"(r[0]), "=r"(r[1]), "=r"(r[2]), "=r"(r[3]) : "r"(a));
}
__device__ __forceinline__ void ldm_x4t(uint32_t* r, uint32_t a) {
    asm volatile("ldmatrix.sync.aligned.m8n8.x4.trans.shared.b16 {%0,%1,%2,%3}, [%4];"
                 : "=r"(r[0]), "=r"(r[1]), "=r"(r[2]), "=r"(r[3]) : "r"(a));
}
__device__ __forceinline__ void mma_bf16(float* d, const uint32_t* a,
                                         const uint32_t* b) {
    asm volatile(
        "mma.sync.aligned.m16n8k16.row.col.f32.bf16.bf16.f32 "
        "{%0,%1,%2,%3}, {%4,%5,%6,%7}, {%8,%9}, {%0,%1,%2,%3};"
        : "+f"(d[0]), "+f"(d[1]), "+f"(d[2]), "+f"(d[3])
        : "r"(a[0]), "r"(a[1]), "r"(a[2]), "r"(a[3]), "r"(b[0]), "r"(b[1]));
}
__device__ __forceinline__ void mma_f16(float* d, const uint32_t* a,
                                        const uint32_t* b) {
    asm volatile(
        "mma.sync.aligned.m16n8k16.row.col.f32.f16.f16.f32 "
        "{%0,%1,%2,%3}, {%4,%5,%6,%7}, {%8,%9}, {%0,%1,%2,%3};"
        : "+f"(d[0]), "+f"(d[1]), "+f"(d[2]), "+f"(d[3])
        : "r"(a[0]), "r"(a[1]), "r"(a[2]), "r"(a[3]), "r"(b[0]), "r"(b[1]));
}
__device__ __forceinline__ uint32_t packbf(float lo, float hi) {
    __nv_bfloat162 t = __floats2bfloat162_rn(lo, hi);
    return *reinterpret_cast<uint32_t*>(&t);
}
__device__ __forceinline__ float lowf(uint32_t u)  { return __uint_as_float(u << 16); }
__device__ __forceinline__ float highf(uint32_t u) { return __uint_as_float(u & 0xFFFF0000u); }
__device__ __forceinline__ uint32_t packh(float f0, float f1) {
    __half2 t = __floats2half2_rn(f0, f1);
    return *reinterpret_cast<uint32_t*>(&t);
}
__device__ __forceinline__ float lowh(uint32_t u) {
    return __low2float(*reinterpret_cast<__half2*>(&u));
}
__device__ __forceinline__ float highh(uint32_t u) {
    return __high2float(*reinterpret_cast<__half2*>(&u));
}

// ---------------------------------------------------------------------------
// Fused prep kernel (unchanged): x-split + both weight transpose-splits.
// ---------------------------------------------------------------------------
__global__ __launch_bounds__(256)
void prep_kernel(const float* __restrict__ x,
                 const float* __restrict__ wq,
                 const float* __restrict__ wp) {
    __shared__ float tile[32][33];
    const int blk = blockIdx.x;
    const int tid = threadIdx.x;

    if (blk < 16384) {
        int i = blk * 256 + tid;
        float v = x[i];
        __nv_bfloat16 h = __float2bfloat16(v);
        g_x_hi[i] = h;
        g_x_lo[i] = __float2bfloat16(v - __bfloat162float(h));
        return;
    }

    const float* w;
    __nv_bfloat16 *oh, *ol;
    int N, bb;
    if (blk < 16384 + 3072) {
        bb = blk - 16384; w = wq; oh = g_wq_hi; ol = g_wq_lo; N = N_QKV;
    } else {
        bb = blk - 19456; w = wp; oh = g_wp_hi; ol = g_wp_lo; N = C_SZ;
    }
    const int nb = (bb % (N / 32)) * 32;
    const int kb = (bb / (N / 32)) * 32;
    const int tx = tid & 31, ty = tid >> 5;
#pragma unroll
    for (int i2 = 0; i2 < 32; i2 += 8)
        tile[ty + i2][tx] = w[(size_t)(kb + ty + i2) * N + nb + tx];
    __syncthreads();
#pragma unroll
    for (int i2 = 0; i2 < 32; i2 += 8) {
        float v = tile[tx][ty + i2];
        __nv_bfloat16 h = __float2bfloat16(v);
        size_t o = (size_t)(nb + ty + i2) * GEMM_K + kb + tx;
        oh[o] = h;
        ol[o] = __float2bfloat16(v - __bfloat162float(h));
    }
}

// ---------------------------------------------------------------------------
// HMMA split-bf16 GEMM v2: 128x64 CTA tile, 128 threads (4 warps, 2x2 grid,
// 64x32 per warp -> 48 independent MMAs per k-step per warp), BK=64,
// 2-stage, 2 CTAs/SM with independent barriers.
// mode 0: epilogue bias + fp16-split scatter (k hi/lo, q hi scaled, v hi/lo)
// mode 1: epilogue bias + fp32 store to out
// ---------------------------------------------------------------------------
#define G_ROWB   144
#define G_ATILE  (128 * G_ROWB)               // 18432
#define G_BTILE  (64 * G_ROWB)                // 9216
#define G_STAGE  (2 * G_ATILE + 2 * G_BTILE)  // 55296
#define GEMM_SMEM (2 * G_STAGE)               // 110592

__global__ __launch_bounds__(128, 2)
void gemm_hmma(const float* __restrict__ bias, float* __restrict__ out,
               int mode) {
    extern __shared__ char smem[];
    const uint32_t sbase = (uint32_t)__cvta_generic_to_shared(smem);
    const int tid = threadIdx.x;
    const int lane = tid & 31, warp = tid >> 5;
    const int wr = warp & 1, wc = warp >> 1;      // 2x2 warp grid
    const int rowBase = blockIdx.y * 128;
    const int colBase = blockIdx.x * 64;

    const __nv_bfloat16 *aSrc[2], *bSrc[2];
    if (mode == 0) { aSrc[0] = g_x_hi;  aSrc[1] = g_x_lo;  bSrc[0] = g_wq_hi; bSrc[1] = g_wq_lo; }
    else           { aSrc[0] = g_ao_hi; aSrc[1] = g_ao_lo; bSrc[0] = g_wp_hi; bSrc[1] = g_wp_lo; }

    float acc[4][4][4];
#pragma unroll
    for (int mt = 0; mt < 4; mt++)
#pragma unroll
        for (int nt = 0; nt < 4; nt++)
#pragma unroll
            for (int q = 0; q < 4; q++) acc[mt][nt][q] = 0.f;

    auto prefetch = [&](int chunk) {
        const int st = chunk & 1;
        const int k0 = chunk * 64;
#pragma unroll
        for (int v = 0; v < 2; v++) {
#pragma unroll
            for (int it = 0; it < 8; it++) {      // A: 1024 pieces / 128 thr
                int p = tid + it * 128;
                int r = p >> 3, cp = p & 7;
                const __nv_bfloat16* g =
                    aSrc[v] + (size_t)(rowBase + r) * GEMM_K + k0 + cp * 8;
                uint32_t d = sbase + (uint32_t)(st * G_STAGE + v * G_ATILE
                                                + r * G_ROWB + cp * 16);
                CP_ASYNC16(d, g);
            }
#pragma unroll
            for (int it = 0; it < 4; it++) {      // B: 512 pieces
                int p = tid + it * 128;
                int r = p >> 3, cp = p & 7;
                const __nv_bfloat16* g =
                    bSrc[v] + (size_t)(colBase + r) * GEMM_K + k0 + cp * 8;
                uint32_t d = sbase + (uint32_t)(st * G_STAGE + 2 * G_ATILE
                                                + v * G_BTILE + r * G_ROWB + cp * 16);
                CP_ASYNC16(d, g);
            }
        }
        CP_COMMIT();
    };

    prefetch(0);

    const int NC = GEMM_K / 64;          // 16
    for (int c = 0; c < NC; c++) {
        CP_WAIT0();
        __syncthreads();
        if (c + 1 < NC) prefetch(c + 1);

        const uint32_t bufBase = sbase + (uint32_t)((c & 1) * G_STAGE);
#pragma unroll
        for (int s = 0; s < 4; s++) {
            uint32_t ah[4][4], al[4][4], bh[2][4], bl[2][4];
            const int akb = s * 32 + ((lane >> 4) & 1) * 16;
            const int arow = wr * 64 + (lane & 7) + ((lane >> 3) & 1) * 8;
#pragma unroll
            for (int mf = 0; mf < 4; mf++) {
                ldm_x4(ah[mf], bufBase + (uint32_t)((arow + mf * 16) * G_ROWB + akb));
                ldm_x4(al[mf], bufBase + (uint32_t)(G_ATILE + (arow + mf * 16) * G_ROWB + akb));
            }
            const int bkb = s * 32 + ((lane >> 3) & 1) * 16;
            const int brow = wc * 32 + ((lane >> 4) & 1) * 8 + (lane & 7);
#pragma unroll
            for (int p2 = 0; p2 < 2; p2++) {
                ldm_x4(bh[p2], bufBase + (uint32_t)(2 * G_ATILE + (brow + p2 * 16) * G_ROWB + bkb));
                ldm_x4(bl[p2], bufBase + (uint32_t)(2 * G_ATILE + G_BTILE + (brow + p2 * 16) * G_ROWB + bkb));
            }

#pragma unroll
            for (int mt = 0; mt < 4; mt++)
#pragma unroll
                for (int nt = 0; nt < 4; nt++) {
                    const uint32_t* bhf = &bh[nt >> 1][(nt & 1) * 2];
                    const uint32_t* blf = &bl[nt >> 1][(nt & 1) * 2];
                    mma_bf16(acc[mt][nt], ah[mt], bhf);
                    mma_bf16(acc[mt][nt], ah[mt], blf);
                    mma_bf16(acc[mt][nt], al[mt], bhf);
                }
        }
    }

    const int r0 = lane >> 2;
    const int c0 = (lane & 3) * 2;
#pragma unroll
    for (int mt = 0; mt < 4; mt++) {
#pragma unroll
        for (int nt = 0; nt < 4; nt++) {
            const int n0 = colBase + wc * 32 + nt * 8 + c0;
            const float b0 = bias[n0], b1 = bias[n0 + 1];
#pragma unroll
            for (int half = 0; half < 2; half++) {
                const int m = rowBase + wr * 64 + mt * 16 + r0 + half * 8;
                float f0 = acc[mt][nt][half * 2 + 0] + b0;
                float f1 = acc[mt][nt][half * 2 + 1] + b1;
                if (mode == 0) {
                    const int bb = m >> 11, t = m & 2047;
                    const int sec = n0 >> 10, cc = n0 & 1023;
                    const int h = cc >> 6, d0 = cc & 63;
                    size_t off = (((size_t)(bb * 16 + h)) * T_SZ + t) * 64 + d0;
                    if (sec == 1) {
                        // q (key-role): hi only, pre-scaled by 1/8
                        *(uint32_t*)(g_q16h + off) = packh(f0 * 0.125f, f1 * 0.125f);
                    } else {
                        __half* dh = (sec == 0) ? g_k16h : g_v16h;
                        __half* dl = (sec == 0) ? g_k16l : g_v16l;
                        uint32_t hi = packh(f0, f1);
                        uint32_t lo = packh(f0 - lowh(hi), f1 - highh(hi));
                        *(uint32_t*)(dh + off) = hi;
                        *(uint32_t*)(dl + off) = lo;
                    }
                } else {
                    float2 v; v.x = f0; v.y = f1;
                    *(float2*)(out + (size_t)m * C_SZ + n0) = v;
                }
            }
        }
    }
}

// ---------------------------------------------------------------------------
// Flash attention v4: fp16 2-pass. 256-row i-tiles (8 warps x 32 rows).
// Source convention wei = K@Q^T: query-role = k (split hi/lo, A side),
// key-role = q (hi only, pre-scaled 0.125, B side).
// S = (Kh+Kl)·Qh  (2 MMA passes);  O = Ph·(Vh+Vl)  (2 MMA passes).
// ---------------------------------------------------------------------------
#define AST   144
#define SQH_O 0
#define SQL_O (256 * AST)              // 36864
#define SKV_O (2 * 256 * AST)          // 73728
#define KVVAR (64 * AST)               // 9216
#define KVBUF (3 * KVVAR)              // 27648 (qh, vh, vl)
#define ATT_SMEM (SKV_O + 2 * KVBUF)   // 129024

__global__ __launch_bounds__(256, 1)
void attn_hmma() {
    extern __shared__ char smem[];
    const uint32_t sbase = (uint32_t)__cvta_generic_to_shared(smem);
    const int tid = threadIdx.x;
    const int lane = tid & 31, w = tid >> 5;
    const int bh = blockIdx.x;
    const int it = (int)(gridDim.y - 1 - blockIdx.y);

    const size_t hbo = (size_t)bh * T_SZ * 64;
    const __half* kvsrc[3] = {g_q16h + hbo, g_v16h + hbo, g_v16l + hbo};

    auto prefetchKV = [&](int jt) {
        const int buf = jt & 1;
#pragma unroll
        for (int i = 0; i < 6; i++) {
            int p = tid + i * 256;               // 0..1535
            int v = p >> 9, rem = p & 511;
            int r = rem >> 3, cp = rem & 7;
            const __half* src = kvsrc[v] + (size_t)(jt * 64 + r) * 64 + cp * 8;
            uint32_t dst = sbase + (uint32_t)(SKV_O + buf * KVBUF + v * KVVAR
                                              + r * AST + cp * 16);
            CP_ASYNC16(dst, src);
        }
        CP_COMMIT();
    };

    prefetchKV(0);

    // resident query-role tile (k hi/lo), plain copy
    {
        const __half* kh = g_k16h + hbo;
        const __half* kl = g_k16l + hbo;
        for (int p = tid; p < 256 * 32; p += 256) {
            int r = p >> 5, c2 = p & 31;
            size_t go = (size_t)(it * 256 + r) * 64 + c2 * 2;
            *(uint32_t*)(smem + SQH_O + r * AST + c2 * 4) = *(const uint32_t*)(kh + go);
            *(uint32_t*)(smem + SQL_O + r * AST + c2 * 4) = *(const uint32_t*)(kl + go);
        }
    }
    __syncthreads();

    float m[2][2], l[2][2];
#pragma unroll
    for (int mt = 0; mt < 2; mt++) { m[mt][0] = m[mt][1] = -1e30f; l[mt][0] = l[mt][1] = 0.f; }
    float O[2][8][4];
#pragma unroll
    for (int mt = 0; mt < 2; mt++)
#pragma unroll
        for (int dt = 0; dt < 8; dt++)
#pragma unroll
            for (int q = 0; q < 4; q++) O[mt][dt][q] = 0.f;

    const int iw = it * 256 + w * 32;
    const int jlast = 4 * it + 3;

    for (int jt = 0; jt <= jlast; jt++) {
        CP_WAIT0();
        __syncthreads();
        if (jt < jlast) prefetchKV(jt + 1);

        if (jt * 64 <= iw + 31) {
            const uint32_t kb = sbase + (uint32_t)(SKV_O + (jt & 1) * KVBUF);
            float s[2][8][4];
#pragma unroll
            for (int mt = 0; mt < 2; mt++)
#pragma unroll
                for (int nt = 0; nt < 8; nt++)
#pragma unroll
                    for (int q = 0; q < 4; q++) s[mt][nt][q] = 0.f;

            // ---- scores: S = (Kh+Kl) @ Qh^T  (2 passes) ----
#pragma unroll
            for (int kk = 0; kk < 4; kk++) {
                uint32_t ah[2][4], al[2][4];
                const int ab = kk * 32 + ((lane >> 4) & 1) * 16;
                const int arow = w * 32 + (lane & 7) + ((lane >> 3) & 1) * 8;
                ldm_x4(ah[0], sbase + (uint32_t)(SQH_O + arow * AST + ab));
                ldm_x4(ah[1], sbase + (uint32_t)(SQH_O + (arow + 16) * AST + ab));
                ldm_x4(al[0], sbase + (uint32_t)(SQL_O + arow * AST + ab));
                ldm_x4(al[1], sbase + (uint32_t)(SQL_O + (arow + 16) * AST + ab));

                const int bb = kk * 32 + ((lane >> 3) & 1) * 16;
                const int br = ((lane >> 4) & 1) * 8 + (lane & 7);
#pragma unroll
                for (int np = 0; np < 4; np++) {
                    uint32_t qf[4];
                    ldm_x4(qf, kb + (uint32_t)((np * 16 + br) * AST + bb));
#pragma unroll
                    for (int mt = 0; mt < 2; mt++) {
                        mma_f16(s[mt][2 * np],     ah[mt], qf + 0);
                        mma_f16(s[mt][2 * np],     al[mt], qf + 0);
                        mma_f16(s[mt][2 * np + 1], ah[mt], qf + 2);
                        mma_f16(s[mt][2 * np + 1], al[mt], qf + 2);
                    }
                }
            }

            // ---- causal mask ----
            const int i0 = iw + (lane >> 2);
            if (jt * 64 + 63 > iw) {
#pragma unroll
                for (int mt = 0; mt < 2; mt++)
#pragma unroll
                    for (int nt = 0; nt < 8; nt++)
#pragma unroll
                        for (int q = 0; q < 4; q++) {
                            int j = jt * 64 + nt * 8 + (lane & 3) * 2 + (q & 1);
                            int i = i0 + mt * 16 + ((q >> 1) ? 8 : 0);
                            if (j > i) s[mt][nt][q] = -1e30f;
                        }
            }

            // ---- online softmax ----
#pragma unroll
            for (int mt = 0; mt < 2; mt++) {
                float mx0 = -1e30f, mx1 = -1e30f;
#pragma unroll
                for (int nt = 0; nt < 8; nt++) {
                    mx0 = fmaxf(mx0, fmaxf(s[mt][nt][0], s[mt][nt][1]));
                    mx1 = fmaxf(mx1, fmaxf(s[mt][nt][2], s[mt][nt][3]));
                }
                mx0 = fmaxf(mx0, __shfl_xor_sync(0xffffffffu, mx0, 1));
                mx0 = fmaxf(mx0, __shfl_xor_sync(0xffffffffu, mx0, 2));
                mx1 = fmaxf(mx1, __shfl_xor_sync(0xffffffffu, mx1, 1));
                mx1 = fmaxf(mx1, __shfl_xor_sync(0xffffffffu, mx1, 2));
                float mn0 = fmaxf(m[mt][0], mx0), mn1 = fmaxf(m[mt][1], mx1);
                float a0 = __expf(m[mt][0] - mn0), a1 = __expf(m[mt][1] - mn1);
                float sum0 = 0.f, sum1 = 0.f;
#pragma unroll
                for (int nt = 0; nt < 8; nt++) {
                    s[mt][nt][0] = __expf(s[mt][nt][0] - mn0);
                    s[mt][nt][1] = __expf(s[mt][nt][1] - mn0);
                    s[mt][nt][2] = __expf(s[mt][nt][2] - mn1);
                    s[mt][nt][3] = __expf(s[mt][nt][3] - mn1);
                    sum0 += s[mt][nt][0] + s[mt][nt][1];
                    sum1 += s[mt][nt][2] + s[mt][nt][3];
                }
                sum0 += __shfl_xor_sync(0xffffffffu, sum0, 1);
                sum0 += __shfl_xor_sync(0xffffffffu, sum0, 2);
                sum1 += __shfl_xor_sync(0xffffffffu, sum1, 1);
                sum1 += __shfl_xor_sync(0xffffffffu, sum1, 2);
                l[mt][0] = l[mt][0] * a0 + sum0;
                l[mt][1] = l[mt][1] * a1 + sum1;
                m[mt][0] = mn0;  m[mt][1] = mn1;
#pragma unroll
                for (int dt = 0; dt < 8; dt++) {
                    O[mt][dt][0] *= a0; O[mt][dt][1] *= a0;
                    O[mt][dt][2] *= a1; O[mt][dt][3] *= a1;
                }
            }

            // ---- PV: O += Ph @ (Vh+Vl)  (2 passes, P hi only) ----
#pragma unroll
            for (int kk = 0; kk < 4; kk++) {
                uint32_t pah[2][4];
#pragma unroll
                for (int mt = 0; mt < 2; mt++)
#pragma unroll
                    for (int t = 0; t < 4; t++) {
                        float f0 = s[mt][2 * kk + (t >> 1)][(t & 1) * 2 + 0];
                        float f1 = s[mt][2 * kk + (t >> 1)][(t & 1) * 2 + 1];
                        pah[mt][t] = packh(f0, f1);
                    }
                const int vrow = kk * 16 + (lane & 7) + ((lane >> 3) & 1) * 8;
                const int voff = ((lane >> 4) & 1) * 16;
#pragma unroll
                for (int dp = 0; dp < 4; dp++) {
                    uint32_t vh4[4], vl4[4];
                    uint32_t a = kb + (uint32_t)(KVVAR + vrow * AST + dp * 32 + voff);
                    ldm_x4t(vh4, a);
                    ldm_x4t(vl4, a + KVVAR);
#pragma unroll
                    for (int mt = 0; mt < 2; mt++) {
                        mma_f16(O[mt][2 * dp],     pah[mt], vh4 + 0);
                        mma_f16(O[mt][2 * dp],     pah[mt], vl4 + 0);
                        mma_f16(O[mt][2 * dp + 1], pah[mt], vh4 + 2);
                        mma_f16(O[mt][2 * dp + 1], pah[mt], vl4 + 2);
                    }
                }
            }
        }
    }

    // ---- epilogue: normalize, bf16-split, write [b][t][C] ----
    const int b = bh >> 4, h = bh & 15;
#pragma unroll
    for (int mt = 0; mt < 2; mt++) {
        const float inv0 = 1.f / l[mt][0], inv1 = 1.f / l[mt][1];
        const int i0 = iw + mt * 16 + (lane >> 2);
#pragma unroll
        for (int dt = 0; dt < 8; dt++) {
            const int col = h * 64 + dt * 8 + (lane & 3) * 2;
            {
                float f0 = O[mt][dt][0] * inv0, f1 = O[mt][dt][1] * inv0;
                uint32_t hi = packbf(f0, f1);
                uint32_t lo = packbf(f0 - lowf(hi), f1 - highf(hi));
                size_t off = ((size_t)(b * T_SZ + i0)) * C_SZ + col;
                *(uint32_t*)(g_ao_hi + off) = hi;
                *(uint32_t*)(g_ao_lo + off) = lo;
            }
            {
                float f0 = O[mt][dt][2] * inv1, f1 = O[mt][dt][3] * inv1;
                uint32_t hi = packbf(f0, f1);
                uint32_t lo = packbf(f0 - lowf(hi), f1 - highf(hi));
                size_t off = ((size_t)(b * T_SZ + i0 + 8)) * C_SZ + col;
                *(uint32_t*)(g_ao_hi + off) = hi;
                *(uint32_t*)(g_ao_lo + off) = lo;
            }
        }
    }
}

// ---------------------------------------------------------------------------
extern "C" void kernel_launch(void* const* d_in, const int* in_sizes, int n_in,
                              void* d_out, int out_size) {
    const float* x        = (const float*)d_in[0];
    const float* c_attn_w = (const float*)d_in[1];
    const float* c_attn_b = (const float*)d_in[2];
    const float* c_proj_w = (const float*)d_in[3];
    const float* c_proj_b = (const float*)d_in[4];
    float* out = (float*)d_out;

    prep_kernel<<<16384 + 3072 + 1024, 256>>>(x, c_attn_w, c_proj_w);

    cudaFuncSetAttribute(gemm_hmma,
                         cudaFuncAttributeMaxDynamicSharedMemorySize, GEMM_SMEM);
    cudaFuncSetAttribute(attn_hmma,
                         cudaFuncAttributeMaxDynamicSharedMemorySize, ATT_SMEM);

    gemm_hmma<<<dim3(N_QKV / 64, M_ROWS / 128), 128, GEMM_SMEM>>>(
        c_attn_b, nullptr, 0);

    attn_hmma<<<dim3(32, T_SZ / 256), 256, ATT_SMEM>>>();

    gemm_hmma<<<dim3(C_SZ / 64, M_ROWS / 128), 128, GEMM_SMEM>>>(
        c_proj_b, out, 1);
}

// round 11
// speedup vs baseline: 1.9507x; 1.0401x over previous
#include <cuda_runtime.h>
#include <cuda_fp16.h>
#include <cstdint>

#define B_SZ   2
#define T_SZ   2048
#define C_SZ   1024
#define M_ROWS 4096
#define N_QKV  3072
#define GEMM_K 1024

// ---------------------------------------------------------------------------
// Scratch (__device__ globals; no allocation allowed). All fp16 now.
// ---------------------------------------------------------------------------
__device__ __half g_x_hi[M_ROWS * C_SZ];
__device__ __half g_x_lo[M_ROWS * C_SZ];
__device__ __half g_wq_hi[N_QKV * GEMM_K];     // transposed [n][k], hi only
__device__ __half g_wp_hi[C_SZ * GEMM_K];      // transposed [n][k], hi only
// qkv for attention: k split (query-role), q hi-only (pre-scaled 1/8), v split
__device__ __half g_k16h[32 * T_SZ * 64], g_k16l[32 * T_SZ * 64];
__device__ __half g_q16h[32 * T_SZ * 64];
__device__ __half g_v16h[32 * T_SZ * 64], g_v16l[32 * T_SZ * 64];
// attention out, fp16 split (proj A side), [b][t][C]
__device__ __half g_ao_hi[M_ROWS * C_SZ], g_ao_lo[M_ROWS * C_SZ];

// ---------------------------------------------------------------------------
// PTX helpers (plain sm_103 target)
// ---------------------------------------------------------------------------
#define CP_ASYNC16(dst, src) \
    asm volatile("cp.async.cg.shared.global [%0], [%1], 16;" :: "r"(dst), "l"(src))
#define CP_COMMIT() asm volatile("cp.async.commit_group;" ::: "memory")
#define CP_WAIT0()  asm volatile("cp.async.wait_group 0;" ::: "memory")

__device__ __forceinline__ void ldm_x4(uint32_t* r, uint32_t a) {
    asm volatile("ldmatrix.sync.aligned.m8n8.x4.shared.b16 {%0,%1,%2,%3}, [%4];"
                 : "=r"(r[0]), "=r"(r[1]), "=r"(r[2]), "=r"(r[3]) : "r"(a));
}
__device__ __forceinline__ void ldm_x4t(uint32_t* r, uint32_t a) {
    asm volatile("ldmatrix.sync.aligned.m8n8.x4.trans.shared.b16 {%0,%1,%2,%3}, [%4];"
                 : "=r"(r[0]), "=r"(r[1]), "=r"(r[2]), "=r"(r[3]) : "r"(a));
}
__device__ __forceinline__ void mma_f16(float* d, const uint32_t* a,
                                        const uint32_t* b) {
    asm volatile(
        "mma.sync.aligned.m16n8k16.row.col.f32.f16.f16.f32 "
        "{%0,%1,%2,%3}, {%4,%5,%6,%7}, {%8,%9}, {%0,%1,%2,%3};"
        : "+f"(d[0]), "+f"(d[1]), "+f"(d[2]), "+f"(d[3])
        : "r"(a[0]), "r"(a[1]), "r"(a[2]), "r"(a[3]), "r"(b[0]), "r"(b[1]));
}
__device__ __forceinline__ uint32_t packh(float f0, float f1) {
    __half2 t = __floats2half2_rn(f0, f1);
    return *reinterpret_cast<uint32_t*>(&t);
}
__device__ __forceinline__ float lowh(uint32_t u) {
    return __low2float(*reinterpret_cast<__half2*>(&u));
}
__device__ __forceinline__ float highh(uint32_t u) {
    return __high2float(*reinterpret_cast<__half2*>(&u));
}

// ---------------------------------------------------------------------------
// Fused prep: x -> fp16 hi/lo split; wq/wp -> transposed fp16 hi only.
// blocks [0,16384): x   [16384,19456): wq   [19456,20480): wp
// ---------------------------------------------------------------------------
__global__ __launch_bounds__(256)
void prep_kernel(const float* __restrict__ x,
                 const float* __restrict__ wq,
                 const float* __restrict__ wp) {
    __shared__ float tile[32][33];
    const int blk = blockIdx.x;
    const int tid = threadIdx.x;

    if (blk < 16384) {
        int i = blk * 256 + tid;
        float v = x[i];
        __half h = __float2half_rn(v);
        g_x_hi[i] = h;
        g_x_lo[i] = __float2half_rn(v - __half2float(h));
        return;
    }

    const float* w;
    __half* oh;
    int N, bb;
    if (blk < 16384 + 3072) {
        bb = blk - 16384; w = wq; oh = g_wq_hi; N = N_QKV;
    } else {
        bb = blk - 19456; w = wp; oh = g_wp_hi; N = C_SZ;
    }
    const int nb = (bb % (N / 32)) * 32;
    const int kb = (bb / (N / 32)) * 32;
    const int tx = tid & 31, ty = tid >> 5;
#pragma unroll
    for (int i2 = 0; i2 < 32; i2 += 8)
        tile[ty + i2][tx] = w[(size_t)(kb + ty + i2) * N + nb + tx];
    __syncthreads();
#pragma unroll
    for (int i2 = 0; i2 < 32; i2 += 8) {
        float v = tile[tx][ty + i2];
        oh[(size_t)(nb + ty + i2) * GEMM_K + kb + tx] = __float2half_rn(v);
    }
}

// ---------------------------------------------------------------------------
// HMMA fp16 2-pass GEMM: C = (Ah+Al) @ Bh^T.  128x128 CTA tile, BK=64,
// 2-stage cp.async, 256 threads (8 warps 4x2, warp 32x64), 2 CTAs/SM.
// Per-CTA L2 traffic: 768KB per 128x128 output (half of round-10's rate).
// mode 0: bias + fp16-split scatter (k hi/lo, q hi*0.125, v hi/lo)
// mode 1: bias + fp32 store
// ---------------------------------------------------------------------------
#define G_ROWB   144                    // 128B data + 16B pad
#define G_TILE   (128 * G_ROWB)         // 18432
#define G_STAGE  (3 * G_TILE)           // 55296 (Ah, Al, Bh)
#define GEMM_SMEM (2 * G_STAGE)         // 110592 -> 2 CTAs/SM

__global__ __launch_bounds__(256, 2)
void gemm_hmma(const float* __restrict__ bias, float* __restrict__ out,
               int mode) {
    extern __shared__ char smem[];
    const uint32_t sbase = (uint32_t)__cvta_generic_to_shared(smem);
    const int tid = threadIdx.x;
    const int lane = tid & 31, warp = tid >> 5;
    const int wr = warp & 3, wc = warp >> 2;      // 4x2 warp grid, warp 32x64
    const int rowBase = blockIdx.y * 128;
    const int colBase = blockIdx.x * 128;

    const __half* srcs[3];
    if (mode == 0) { srcs[0] = g_x_hi;  srcs[1] = g_x_lo;  srcs[2] = g_wq_hi; }
    else           { srcs[0] = g_ao_hi; srcs[1] = g_ao_lo; srcs[2] = g_wp_hi; }
    const int rbase[3] = {rowBase, rowBase, colBase};

    float acc[2][8][4];
#pragma unroll
    for (int mt = 0; mt < 2; mt++)
#pragma unroll
        for (int nt = 0; nt < 8; nt++)
#pragma unroll
            for (int q = 0; q < 4; q++) acc[mt][nt][q] = 0.f;

    // per chunk: 3 tiles x 128 rows x 128B = 48KB; thread: 12 x 16B
    auto prefetch = [&](int chunk) {
        const int st = chunk & 1;
        const int k0 = chunk * 64;
#pragma unroll
        for (int v = 0; v < 3; v++) {
#pragma unroll
            for (int it = 0; it < 4; it++) {
                int p = tid + it * 256;            // 0..1023
                int r = p >> 3, cp = p & 7;
                const __half* g =
                    srcs[v] + (size_t)(rbase[v] + r) * GEMM_K + k0 + cp * 8;
                uint32_t d = sbase + (uint32_t)(st * G_STAGE + v * G_TILE
                                                + r * G_ROWB + cp * 16);
                CP_ASYNC16(d, g);
            }
        }
        CP_COMMIT();
    };

    prefetch(0);

    const int NC = GEMM_K / 64;          // 16
    for (int c = 0; c < NC; c++) {
        CP_WAIT0();
        __syncthreads();                  // all warps done with stage (c-1)&1
        if (c + 1 < NC) prefetch(c + 1);  // writes stage (c+1)&1 = (c-1)&1: safe

        const uint32_t bufBase = sbase + (uint32_t)((c & 1) * G_STAGE);
#pragma unroll
        for (int s = 0; s < 4; s++) {
            uint32_t ah[2][4], al[2][4], bh[4][4];
            const int akb = s * 32 + ((lane >> 4) & 1) * 16;
            const int arow = wr * 32 + (lane & 7) + ((lane >> 3) & 1) * 8;
            ldm_x4(ah[0], bufBase + (uint32_t)(arow * G_ROWB + akb));
            ldm_x4(ah[1], bufBase + (uint32_t)((arow + 16) * G_ROWB + akb));
            ldm_x4(al[0], bufBase + (uint32_t)(G_TILE + arow * G_ROWB + akb));
            ldm_x4(al[1], bufBase + (uint32_t)(G_TILE + (arow + 16) * G_ROWB + akb));

            const int bkb = s * 32 + ((lane >> 3) & 1) * 16;
            const int brow = wc * 64 + ((lane >> 4) & 1) * 8 + (lane & 7);
#pragma unroll
            for (int p2 = 0; p2 < 4; p2++)
                ldm_x4(bh[p2], bufBase + (uint32_t)(2 * G_TILE + (brow + p2 * 16) * G_ROWB + bkb));

#pragma unroll
            for (int mt = 0; mt < 2; mt++)
#pragma unroll
                for (int nt = 0; nt < 8; nt++) {
                    const uint32_t* bhf = &bh[nt >> 1][(nt & 1) * 2];
                    mma_f16(acc[mt][nt], ah[mt], bhf);
                    mma_f16(acc[mt][nt], al[mt], bhf);
                }
        }
    }

    const int r0 = lane >> 2;
    const int c0 = (lane & 3) * 2;
#pragma unroll
    for (int mt = 0; mt < 2; mt++) {
#pragma unroll
        for (int nt = 0; nt < 8; nt++) {
            const int n0 = colBase + wc * 64 + nt * 8 + c0;
            const float b0 = bias[n0], b1 = bias[n0 + 1];
#pragma unroll
            for (int half = 0; half < 2; half++) {
                const int m = rowBase + wr * 32 + mt * 16 + r0 + half * 8;
                float f0 = acc[mt][nt][half * 2 + 0] + b0;
                float f1 = acc[mt][nt][half * 2 + 1] + b1;
                if (mode == 0) {
                    const int bb = m >> 11, t = m & 2047;
                    const int sec = n0 >> 10, cc = n0 & 1023;
                    const int h = cc >> 6, d0 = cc & 63;
                    size_t off = (((size_t)(bb * 16 + h)) * T_SZ + t) * 64 + d0;
                    if (sec == 1) {
                        *(uint32_t*)(g_q16h + off) = packh(f0 * 0.125f, f1 * 0.125f);
                    } else {
                        __half* dh = (sec == 0) ? g_k16h : g_v16h;
                        __half* dl = (sec == 0) ? g_k16l : g_v16l;
                        uint32_t hi = packh(f0, f1);
                        uint32_t lo = packh(f0 - lowh(hi), f1 - highh(hi));
                        *(uint32_t*)(dh + off) = hi;
                        *(uint32_t*)(dl + off) = lo;
                    }
                } else {
                    float2 v; v.x = f0; v.y = f1;
                    *(float2*)(out + (size_t)m * C_SZ + n0) = v;
                }
            }
        }
    }
}

// ---------------------------------------------------------------------------
// Flash attention (round-10 fp16 2-pass, unchanged except ao epilogue dtype).
// 256-row i-tiles, 8 warps x 32 rows. wei = K@Q^T: query-role = k (split),
// key-role = q (hi, pre-scaled). S = (Kh+Kl)·Qh;  O = Ph·(Vh+Vl).
// ---------------------------------------------------------------------------
#define AST   144
#define SQH_O 0
#define SQL_O (256 * AST)
#define SKV_O (2 * 256 * AST)          // 73728
#define KVVAR (64 * AST)               // 9216
#define KVBUF (3 * KVVAR)              // 27648 (qh, vh, vl)
#define ATT_SMEM (SKV_O + 2 * KVBUF)   // 129024

__global__ __launch_bounds__(256, 1)
void attn_hmma() {
    extern __shared__ char smem[];
    const uint32_t sbase = (uint32_t)__cvta_generic_to_shared(smem);
    const int tid = threadIdx.x;
    const int lane = tid & 31, w = tid >> 5;
    const int bh = blockIdx.x;
    const int it = (int)(gridDim.y - 1 - blockIdx.y);

    const size_t hbo = (size_t)bh * T_SZ * 64;
    const __half* kvsrc[3] = {g_q16h + hbo, g_v16h + hbo, g_v16l + hbo};

    auto prefetchKV = [&](int jt) {
        const int buf = jt & 1;
#pragma unroll
        for (int i = 0; i < 6; i++) {
            int p = tid + i * 256;
            int v = p >> 9, rem = p & 511;
            int r = rem >> 3, cp = rem & 7;
            const __half* src = kvsrc[v] + (size_t)(jt * 64 + r) * 64 + cp * 8;
            uint32_t dst = sbase + (uint32_t)(SKV_O + buf * KVBUF + v * KVVAR
                                              + r * AST + cp * 16);
            CP_ASYNC16(dst, src);
        }
        CP_COMMIT();
    };

    prefetchKV(0);

    {
        const __half* kh = g_k16h + hbo;
        const __half* kl = g_k16l + hbo;
        for (int p = tid; p < 256 * 32; p += 256) {
            int r = p >> 5, c2 = p & 31;
            size_t go = (size_t)(it * 256 + r) * 64 + c2 * 2;
            *(uint32_t*)(smem + SQH_O + r * AST + c2 * 4) = *(const uint32_t*)(kh + go);
            *(uint32_t*)(smem + SQL_O + r * AST + c2 * 4) = *(const uint32_t*)(kl + go);
        }
    }
    __syncthreads();

    float m[2][2], l[2][2];
#pragma unroll
    for (int mt = 0; mt < 2; mt++) { m[mt][0] = m[mt][1] = -1e30f; l[mt][0] = l[mt][1] = 0.f; }
    float O[2][8][4];
#pragma unroll
    for (int mt = 0; mt < 2; mt++)
#pragma unroll
        for (int dt = 0; dt < 8; dt++)
#pragma unroll
            for (int q = 0; q < 4; q++) O[mt][dt][q] = 0.f;

    const int iw = it * 256 + w * 32;
    const int jlast = 4 * it + 3;

    for (int jt = 0; jt <= jlast; jt++) {
        CP_WAIT0();
        __syncthreads();
        if (jt < jlast) prefetchKV(jt + 1);

        if (jt * 64 <= iw + 31) {
            const uint32_t kb = sbase + (uint32_t)(SKV_O + (jt & 1) * KVBUF);
            float s[2][8][4];
#pragma unroll
            for (int mt = 0; mt < 2; mt++)
#pragma unroll
                for (int nt = 0; nt < 8; nt++)
#pragma unroll
                    for (int q = 0; q < 4; q++) s[mt][nt][q] = 0.f;

#pragma unroll
            for (int kk = 0; kk < 4; kk++) {
                uint32_t ah[2][4], al[2][4];
                const int ab = kk * 32 + ((lane >> 4) & 1) * 16;
                const int arow = w * 32 + (lane & 7) + ((lane >> 3) & 1) * 8;
                ldm_x4(ah[0], sbase + (uint32_t)(SQH_O + arow * AST + ab));
                ldm_x4(ah[1], sbase + (uint32_t)(SQH_O + (arow + 16) * AST + ab));
                ldm_x4(al[0], sbase + (uint32_t)(SQL_O + arow * AST + ab));
                ldm_x4(al[1], sbase + (uint32_t)(SQL_O + (arow + 16) * AST + ab));

                const int bb = kk * 32 + ((lane >> 3) & 1) * 16;
                const int br = ((lane >> 4) & 1) * 8 + (lane & 7);
#pragma unroll
                for (int np = 0; np < 4; np++) {
                    uint32_t qf[4];
                    ldm_x4(qf, kb + (uint32_t)((np * 16 + br) * AST + bb));
#pragma unroll
                    for (int mt = 0; mt < 2; mt++) {
                        mma_f16(s[mt][2 * np],     ah[mt], qf + 0);
                        mma_f16(s[mt][2 * np],     al[mt], qf + 0);
                        mma_f16(s[mt][2 * np + 1], ah[mt], qf + 2);
                        mma_f16(s[mt][2 * np + 1], al[mt], qf + 2);
                    }
                }
            }

            const int i0 = iw + (lane >> 2);
            if (jt * 64 + 63 > iw) {
#pragma unroll
                for (int mt = 0; mt < 2; mt++)
#pragma unroll
                    for (int nt = 0; nt < 8; nt++)
#pragma unroll
                        for (int q = 0; q < 4; q++) {
                            int j = jt * 64 + nt * 8 + (lane & 3) * 2 + (q & 1);
                            int i = i0 + mt * 16 + ((q >> 1) ? 8 : 0);
                            if (j > i) s[mt][nt][q] = -1e30f;
                        }
            }

#pragma unroll
            for (int mt = 0; mt < 2; mt++) {
                float mx0 = -1e30f, mx1 = -1e30f;
#pragma unroll
                for (int nt = 0; nt < 8; nt++) {
                    mx0 = fmaxf(mx0, fmaxf(s[mt][nt][0], s[mt][nt][1]));
                    mx1 = fmaxf(mx1, fmaxf(s[mt][nt][2], s[mt][nt][3]));
                }
                mx0 = fmaxf(mx0, __shfl_xor_sync(0xffffffffu, mx0, 1));
                mx0 = fmaxf(mx0, __shfl_xor_sync(0xffffffffu, mx0, 2));
                mx1 = fmaxf(mx1, __shfl_xor_sync(0xffffffffu, mx1, 1));
                mx1 = fmaxf(mx1, __shfl_xor_sync(0xffffffffu, mx1, 2));
                float mn0 = fmaxf(m[mt][0], mx0), mn1 = fmaxf(m[mt][1], mx1);
                float a0 = __expf(m[mt][0] - mn0), a1 = __expf(m[mt][1] - mn1);
                float sum0 = 0.f, sum1 = 0.f;
#pragma unroll
                for (int nt = 0; nt < 8; nt++) {
                    s[mt][nt][0] = __expf(s[mt][nt][0] - mn0);
                    s[mt][nt][1] = __expf(s[mt][nt][1] - mn0);
                    s[mt][nt][2] = __expf(s[mt][nt][2] - mn1);
                    s[mt][nt][3] = __expf(s[mt][nt][3] - mn1);
                    sum0 += s[mt][nt][0] + s[mt][nt][1];
                    sum1 += s[mt][nt][2] + s[mt][nt][3];
                }
                sum0 += __shfl_xor_sync(0xffffffffu, sum0, 1);
                sum0 += __shfl_xor_sync(0xffffffffu, sum0, 2);
                sum1 += __shfl_xor_sync(0xffffffffu, sum1, 1);
                sum1 += __shfl_xor_sync(0xffffffffu, sum1, 2);
                l[mt][0] = l[mt][0] * a0 + sum0;
                l[mt][1] = l[mt][1] * a1 + sum1;
                m[mt][0] = mn0;  m[mt][1] = mn1;
#pragma unroll
                for (int dt = 0; dt < 8; dt++) {
                    O[mt][dt][0] *= a0; O[mt][dt][1] *= a0;
                    O[mt][dt][2] *= a1; O[mt][dt][3] *= a1;
                }
            }

#pragma unroll
            for (int kk = 0; kk < 4; kk++) {
                uint32_t pah[2][4];
#pragma unroll
                for (int mt = 0; mt < 2; mt++)
#pragma unroll
                    for (int t = 0; t < 4; t++) {
                        float f0 = s[mt][2 * kk + (t >> 1)][(t & 1) * 2 + 0];
                        float f1 = s[mt][2 * kk + (t >> 1)][(t & 1) * 2 + 1];
                        pah[mt][t] = packh(f0, f1);
                    }
                const int vrow = kk * 16 + (lane & 7) + ((lane >> 3) & 1) * 8;
                const int voff = ((lane >> 4) & 1) * 16;
#pragma unroll
                for (int dp = 0; dp < 4; dp++) {
                    uint32_t vh4[4], vl4[4];
                    uint32_t a = kb + (uint32_t)(KVVAR + vrow * AST + dp * 32 + voff);
                    ldm_x4t(vh4, a);
                    ldm_x4t(vl4, a + KVVAR);
#pragma unroll
                    for (int mt = 0; mt < 2; mt++) {
                        mma_f16(O[mt][2 * dp],     pah[mt], vh4 + 0);
                        mma_f16(O[mt][2 * dp],     pah[mt], vl4 + 0);
                        mma_f16(O[mt][2 * dp + 1], pah[mt], vh4 + 2);
                        mma_f16(O[mt][2 * dp + 1], pah[mt], vl4 + 2);
                    }
                }
            }
        }
    }

    // epilogue: normalize, fp16-split, write [b][t][C]
    const int b = bh >> 4, h = bh & 15;
#pragma unroll
    for (int mt = 0; mt < 2; mt++) {
        const float inv0 = 1.f / l[mt][0], inv1 = 1.f / l[mt][1];
        const int i0 = iw + mt * 16 + (lane >> 2);
#pragma unroll
        for (int dt = 0; dt < 8; dt++) {
            const int col = h * 64 + dt * 8 + (lane & 3) * 2;
            {
                float f0 = O[mt][dt][0] * inv0, f1 = O[mt][dt][1] * inv0;
                uint32_t hi = packh(f0, f1);
                uint32_t lo = packh(f0 - lowh(hi), f1 - highh(hi));
                size_t off = ((size_t)(b * T_SZ + i0)) * C_SZ + col;
                *(uint32_t*)(g_ao_hi + off) = hi;
                *(uint32_t*)(g_ao_lo + off) = lo;
            }
            {
                float f0 = O[mt][dt][2] * inv1, f1 = O[mt][dt][3] * inv1;
                uint32_t hi = packh(f0, f1);
                uint32_t lo = packh(f0 - lowh(hi), f1 - highh(hi));
                size_t off = ((size_t)(b * T_SZ + i0 + 8)) * C_SZ + col;
                *(uint32_t*)(g_ao_hi + off) = hi;
                *(uint32_t*)(g_ao_lo + off) = lo;
            }
        }
    }
}

// ---------------------------------------------------------------------------
extern "C" void kernel_launch(void* const* d_in, const int* in_sizes, int n_in,
                              void* d_out, int out_size) {
    const float* x        = (const float*)d_in[0];
    const float* c_attn_w = (const float*)d_in[1];
    const float* c_attn_b = (const float*)d_in[2];
    const float* c_proj_w = (const float*)d_in[3];
    const float* c_proj_b = (const float*)d_in[4];
    float* out = (float*)d_out;

    prep_kernel<<<16384 + 3072 + 1024, 256>>>(x, c_attn_w, c_proj_w);

    cudaFuncSetAttribute(gemm_hmma,
                         cudaFuncAttributeMaxDynamicSharedMemorySize, GEMM_SMEM);
    cudaFuncSetAttribute(attn_hmma,
                         cudaFuncAttributeMaxDynamicSharedMemorySize, ATT_SMEM);

    // QKV: grid (24, 32)
    gemm_hmma<<<dim3(N_QKV / 128, M_ROWS / 128), 256, GEMM_SMEM>>>(
        c_attn_b, nullptr, 0);

    attn_hmma<<<dim3(32, T_SZ / 256), 256, ATT_SMEM>>>();

    // Proj: grid (8, 32)
    gemm_hmma<<<dim3(C_SZ / 128, M_ROWS / 128), 256, GEMM_SMEM>>>(
        c_proj_b, out, 1);
}

// round 12
// speedup vs baseline: 3.3031x; 1.6933x over previous
#include <cuda_runtime.h>
#include <cuda_fp16.h>
#include <cstdint>

#define B_SZ   2
#define T_SZ   2048
#define C_SZ   1024
#define M_ROWS 4096
#define N_QKV  3072
#define GEMM_K 1024

// ---------------------------------------------------------------------------
// Scratch (__device__ globals; no allocation allowed). All fp16.
// ---------------------------------------------------------------------------
__device__ __half g_x_hi[M_ROWS * C_SZ];
__device__ __half g_wq_hi[N_QKV * GEMM_K];     // transposed [n][k]
__device__ __half g_wp_hi[C_SZ * GEMM_K];      // transposed [n][k]
// qkv for attention: k split (query-role), q hi-only (pre-scaled 1/8), v split
__device__ __half g_k16h[32 * T_SZ * 64], g_k16l[32 * T_SZ * 64];
__device__ __half g_q16h[32 * T_SZ * 64];
__device__ __half g_v16h[32 * T_SZ * 64], g_v16l[32 * T_SZ * 64];
// attention out, fp16 hi only (proj A side), [b][t][C]
__device__ __half g_ao_hi[M_ROWS * C_SZ];

// ---------------------------------------------------------------------------
// PTX helpers (plain sm_103 target)
// ---------------------------------------------------------------------------
#define CP_ASYNC16(dst, src) \
    asm volatile("cp.async.cg.shared.global [%0], [%1], 16;" :: "r"(dst), "l"(src))
#define CP_COMMIT() asm volatile("cp.async.commit_group;" ::: "memory")
#define CP_WAIT1()  asm volatile("cp.async.wait_group 1;" ::: "memory")
#define CP_WAIT0()  asm volatile("cp.async.wait_group 0;" ::: "memory")

__device__ __forceinline__ void ldm_x4(uint32_t* r, uint32_t a) {
    asm volatile("ldmatrix.sync.aligned.m8n8.x4.shared.b16 {%0,%1,%2,%3}, [%4];"
                 : "=r"(r[0]), "=r"(r[1]), "=r"(r[2]), "=r"(r[3]) : "r"(a));
}
__device__ __forceinline__ void ldm_x4t(uint32_t* r, uint32_t a) {
    asm volatile("ldmatrix.sync.aligned.m8n8.x4.trans.shared.b16 {%0,%1,%2,%3}, [%4];"
                 : "=r"(r[0]), "=r"(r[1]), "=r"(r[2]), "=r"(r[3]) : "r"(a));
}
__device__ __forceinline__ void mma_f16(float* d, const uint32_t* a,
                                        const uint32_t* b) {
    asm volatile(
        "mma.sync.aligned.m16n8k16.row.col.f32.f16.f16.f32 "
        "{%0,%1,%2,%3}, {%4,%5,%6,%7}, {%8,%9}, {%0,%1,%2,%3};"
        : "+f"(d[0]), "+f"(d[1]), "+f"(d[2]), "+f"(d[3])
        : "r"(a[0]), "r"(a[1]), "r"(a[2]), "r"(a[3]), "r"(b[0]), "r"(b[1]));
}
__device__ __forceinline__ uint32_t packh(float f0, float f1) {
    __half2 t = __floats2half2_rn(f0, f1);
    return *reinterpret_cast<uint32_t*>(&t);
}
__device__ __forceinline__ float lowh(uint32_t u) {
    return __low2float(*reinterpret_cast<__half2*>(&u));
}
__device__ __forceinline__ float highh(uint32_t u) {
    return __high2float(*reinterpret_cast<__half2*>(&u));
}

// ---------------------------------------------------------------------------
// Fused prep: x -> fp16 hi; wq/wp -> transposed fp16 hi.
// blocks [0,16384): x   [16384,19456): wq   [19456,20480): wp
// ---------------------------------------------------------------------------
__global__ __launch_bounds__(256)
void prep_kernel(const float* __restrict__ x,
                 const float* __restrict__ wq,
                 const float* __restrict__ wp) {
    __shared__ float tile[32][33];
    const int blk = blockIdx.x;
    const int tid = threadIdx.x;

    if (blk < 16384) {
        int i = blk * 256 + tid;
        g_x_hi[i] = __float2half_rn(x[i]);
        return;
    }

    const float* w;
    __half* oh;
    int N, bb;
    if (blk < 16384 + 3072) {
        bb = blk - 16384; w = wq; oh = g_wq_hi; N = N_QKV;
    } else {
        bb = blk - 19456; w = wp; oh = g_wp_hi; N = C_SZ;
    }
    const int nb = (bb % (N / 32)) * 32;
    const int kb = (bb / (N / 32)) * 32;
    const int tx = tid & 31, ty = tid >> 5;
#pragma unroll
    for (int i2 = 0; i2 < 32; i2 += 8)
        tile[ty + i2][tx] = w[(size_t)(kb + ty + i2) * N + nb + tx];
    __syncthreads();
#pragma unroll
    for (int i2 = 0; i2 < 32; i2 += 8)
        oh[(size_t)(nb + ty + i2) * GEMM_K + kb + tx] =
            __float2half_rn(tile[tx][ty + i2]);
}

// ---------------------------------------------------------------------------
// HMMA 1-pass fp16 GEMM: C = Ah @ Bh^T.  128x128 CTA tile, BK=64, 3-stage
// cp.async, 256 threads (8 warps 4x2, warp 32x64), 2 CTAs/SM.
// mode 0: bias + fp16-split scatter (k hi/lo, q hi*0.125, v hi/lo)
// mode 1: bias + fp32 store
// ---------------------------------------------------------------------------
#define G_ROWB   144                    // 128B data + 16B pad
#define G_TILE   (128 * G_ROWB)         // 18432
#define G_STAGE  (2 * G_TILE)           // 36864 (Ah, Bh)
#define GEMM_SMEM (3 * G_STAGE)         // 110592 -> 2 CTAs/SM

__global__ __launch_bounds__(256, 2)
void gemm_hmma(const float* __restrict__ bias, float* __restrict__ out,
               int mode) {
    extern __shared__ char smem[];
    const uint32_t sbase = (uint32_t)__cvta_generic_to_shared(smem);
    const int tid = threadIdx.x;
    const int lane = tid & 31, warp = tid >> 5;
    const int wr = warp & 3, wc = warp >> 2;      // 4x2 warp grid, warp 32x64
    const int rowBase = blockIdx.y * 128;
    const int colBase = blockIdx.x * 128;

    const __half* srcs[2];
    if (mode == 0) { srcs[0] = g_x_hi;  srcs[1] = g_wq_hi; }
    else           { srcs[0] = g_ao_hi; srcs[1] = g_wp_hi; }
    const int rbase[2] = {rowBase, colBase};

    float acc[2][8][4];
#pragma unroll
    for (int mt = 0; mt < 2; mt++)
#pragma unroll
        for (int nt = 0; nt < 8; nt++)
#pragma unroll
            for (int q = 0; q < 4; q++) acc[mt][nt][q] = 0.f;

    // per chunk: 2 tiles x 128 rows x 128B = 32KB; thread: 8 x 16B
    auto prefetch = [&](int chunk) {
        const int st = chunk % 3;
        const int k0 = chunk * 64;
#pragma unroll
        for (int v = 0; v < 2; v++) {
#pragma unroll
            for (int it = 0; it < 4; it++) {
                int p = tid + it * 256;            // 0..1023
                int r = p >> 3, cp = p & 7;
                const __half* g =
                    srcs[v] + (size_t)(rbase[v] + r) * GEMM_K + k0 + cp * 8;
                uint32_t d = sbase + (uint32_t)(st * G_STAGE + v * G_TILE
                                                + r * G_ROWB + cp * 16);
                CP_ASYNC16(d, g);
            }
        }
        CP_COMMIT();
    };

    prefetch(0);
    prefetch(1);

    const int NC = GEMM_K / 64;          // 16
    for (int c = 0; c < NC; c++) {
        if (c + 1 < NC) { CP_WAIT1(); } else { CP_WAIT0(); }
        __syncthreads();                  // all warps done reading stage (c-1)%3
        if (c + 2 < NC) prefetch(c + 2);  // writes stage (c+2)%3 = (c-1)%3: safe

        const uint32_t bufBase = sbase + (uint32_t)((c % 3) * G_STAGE);
#pragma unroll
        for (int s = 0; s < 4; s++) {
            uint32_t ah[2][4], bh[4][4];
            const int akb = s * 32 + ((lane >> 4) & 1) * 16;
            const int arow = wr * 32 + (lane & 7) + ((lane >> 3) & 1) * 8;
            ldm_x4(ah[0], bufBase + (uint32_t)(arow * G_ROWB + akb));
            ldm_x4(ah[1], bufBase + (uint32_t)((arow + 16) * G_ROWB + akb));

            const int bkb = s * 32 + ((lane >> 3) & 1) * 16;
            const int brow = wc * 64 + ((lane >> 4) & 1) * 8 + (lane & 7);
#pragma unroll
            for (int p2 = 0; p2 < 4; p2++)
                ldm_x4(bh[p2], bufBase + (uint32_t)(G_TILE + (brow + p2 * 16) * G_ROWB + bkb));

#pragma unroll
            for (int mt = 0; mt < 2; mt++)
#pragma unroll
                for (int nt = 0; nt < 8; nt++)
                    mma_f16(acc[mt][nt], ah[mt], &bh[nt >> 1][(nt & 1) * 2]);
        }
    }

    const int r0 = lane >> 2;
    const int c0 = (lane & 3) * 2;
#pragma unroll
    for (int mt = 0; mt < 2; mt++) {
#pragma unroll
        for (int nt = 0; nt < 8; nt++) {
            const int n0 = colBase + wc * 64 + nt * 8 + c0;
            const float b0 = bias[n0], b1 = bias[n0 + 1];
#pragma unroll
            for (int half = 0; half < 2; half++) {
                const int m = rowBase + wr * 32 + mt * 16 + r0 + half * 8;
                float f0 = acc[mt][nt][half * 2 + 0] + b0;
                float f1 = acc[mt][nt][half * 2 + 1] + b1;
                if (mode == 0) {
                    const int bb = m >> 11, t = m & 2047;
                    const int sec = n0 >> 10, cc = n0 & 1023;
                    const int h = cc >> 6, d0 = cc & 63;
                    size_t off = (((size_t)(bb * 16 + h)) * T_SZ + t) * 64 + d0;
                    if (sec == 1) {
                        *(uint32_t*)(g_q16h + off) = packh(f0 * 0.125f, f1 * 0.125f);
                    } else {
                        __half* dh = (sec == 0) ? g_k16h : g_v16h;
                        __half* dl = (sec == 0) ? g_k16l : g_v16l;
                        uint32_t hi = packh(f0, f1);
                        uint32_t lo = packh(f0 - lowh(hi), f1 - highh(hi));
                        *(uint32_t*)(dh + off) = hi;
                        *(uint32_t*)(dl + off) = lo;
                    }
                } else {
                    float2 v; v.x = f0; v.y = f1;
                    *(float2*)(out + (size_t)m * C_SZ + n0) = v;
                }
            }
        }
    }
}

// ---------------------------------------------------------------------------
// Flash attention (fp16 2-pass, unchanged except ao epilogue hi-only).
// 256-row i-tiles, 8 warps x 32 rows. wei = K@Q^T: query-role = k (split),
// key-role = q (hi, pre-scaled). S = (Kh+Kl)·Qh;  O = Ph·(Vh+Vl).
// ---------------------------------------------------------------------------
#define AST   144
#define SQH_O 0
#define SQL_O (256 * AST)
#define SKV_O (2 * 256 * AST)          // 73728
#define KVVAR (64 * AST)               // 9216
#define KVBUF (3 * KVVAR)              // 27648 (qh, vh, vl)
#define ATT_SMEM (SKV_O + 2 * KVBUF)   // 129024

__global__ __launch_bounds__(256, 1)
void attn_hmma() {
    extern __shared__ char smem[];
    const uint32_t sbase = (uint32_t)__cvta_generic_to_shared(smem);
    const int tid = threadIdx.x;
    const int lane = tid & 31, w = tid >> 5;
    const int bh = blockIdx.x;
    const int it = (int)(gridDim.y - 1 - blockIdx.y);

    const size_t hbo = (size_t)bh * T_SZ * 64;
    const __half* kvsrc[3] = {g_q16h + hbo, g_v16h + hbo, g_v16l + hbo};

    auto prefetchKV = [&](int jt) {
        const int buf = jt & 1;
#pragma unroll
        for (int i = 0; i < 6; i++) {
            int p = tid + i * 256;
            int v = p >> 9, rem = p & 511;
            int r = rem >> 3, cp = rem & 7;
            const __half* src = kvsrc[v] + (size_t)(jt * 64 + r) * 64 + cp * 8;
            uint32_t dst = sbase + (uint32_t)(SKV_O + buf * KVBUF + v * KVVAR
                                              + r * AST + cp * 16);
            CP_ASYNC16(dst, src);
        }
        CP_COMMIT();
    };

    prefetchKV(0);

    {
        const __half* kh = g_k16h + hbo;
        const __half* kl = g_k16l + hbo;
        for (int p = tid; p < 256 * 32; p += 256) {
            int r = p >> 5, c2 = p & 31;
            size_t go = (size_t)(it * 256 + r) * 64 + c2 * 2;
            *(uint32_t*)(smem + SQH_O + r * AST + c2 * 4) = *(const uint32_t*)(kh + go);
            *(uint32_t*)(smem + SQL_O + r * AST + c2 * 4) = *(const uint32_t*)(kl + go);
        }
    }
    __syncthreads();

    float m[2][2], l[2][2];
#pragma unroll
    for (int mt = 0; mt < 2; mt++) { m[mt][0] = m[mt][1] = -1e30f; l[mt][0] = l[mt][1] = 0.f; }
    float O[2][8][4];
#pragma unroll
    for (int mt = 0; mt < 2; mt++)
#pragma unroll
        for (int dt = 0; dt < 8; dt++)
#pragma unroll
            for (int q = 0; q < 4; q++) O[mt][dt][q] = 0.f;

    const int iw = it * 256 + w * 32;
    const int jlast = 4 * it + 3;

    for (int jt = 0; jt <= jlast; jt++) {
        CP_WAIT0();
        __syncthreads();
        if (jt < jlast) prefetchKV(jt + 1);

        if (jt * 64 <= iw + 31) {
            const uint32_t kb = sbase + (uint32_t)(SKV_O + (jt & 1) * KVBUF);
            float s[2][8][4];
#pragma unroll
            for (int mt = 0; mt < 2; mt++)
#pragma unroll
                for (int nt = 0; nt < 8; nt++)
#pragma unroll
                    for (int q = 0; q < 4; q++) s[mt][nt][q] = 0.f;

#pragma unroll
            for (int kk = 0; kk < 4; kk++) {
                uint32_t ah[2][4], al[2][4];
                const int ab = kk * 32 + ((lane >> 4) & 1) * 16;
                const int arow = w * 32 + (lane & 7) + ((lane >> 3) & 1) * 8;
                ldm_x4(ah[0], sbase + (uint32_t)(SQH_O + arow * AST + ab));
                ldm_x4(ah[1], sbase + (uint32_t)(SQH_O + (arow + 16) * AST + ab));
                ldm_x4(al[0], sbase + (uint32_t)(SQL_O + arow * AST + ab));
                ldm_x4(al[1], sbase + (uint32_t)(SQL_O + (arow + 16) * AST + ab));

                const int bb = kk * 32 + ((lane >> 3) & 1) * 16;
                const int br = ((lane >> 4) & 1) * 8 + (lane & 7);
#pragma unroll
                for (int np = 0; np < 4; np++) {
                    uint32_t qf[4];
                    ldm_x4(qf, kb + (uint32_t)((np * 16 + br) * AST + bb));
#pragma unroll
                    for (int mt = 0; mt < 2; mt++) {
                        mma_f16(s[mt][2 * np],     ah[mt], qf + 0);
                        mma_f16(s[mt][2 * np],     al[mt], qf + 0);
                        mma_f16(s[mt][2 * np + 1], ah[mt], qf + 2);
                        mma_f16(s[mt][2 * np + 1], al[mt], qf + 2);
                    }
                }
            }

            const int i0 = iw + (lane >> 2);
            if (jt * 64 + 63 > iw) {
#pragma unroll
                for (int mt = 0; mt < 2; mt++)
#pragma unroll
                    for (int nt = 0; nt < 8; nt++)
#pragma unroll
                        for (int q = 0; q < 4; q++) {
                            int j = jt * 64 + nt * 8 + (lane & 3) * 2 + (q & 1);
                            int i = i0 + mt * 16 + ((q >> 1) ? 8 : 0);
                            if (j > i) s[mt][nt][q] = -1e30f;
                        }
            }

#pragma unroll
            for (int mt = 0; mt < 2; mt++) {
                float mx0 = -1e30f, mx1 = -1e30f;
#pragma unroll
                for (int nt = 0; nt < 8; nt++) {
                    mx0 = fmaxf(mx0, fmaxf(s[mt][nt][0], s[mt][nt][1]));
                    mx1 = fmaxf(mx1, fmaxf(s[mt][nt][2], s[mt][nt][3]));
                }
                mx0 = fmaxf(mx0, __shfl_xor_sync(0xffffffffu, mx0, 1));
                mx0 = fmaxf(mx0, __shfl_xor_sync(0xffffffffu, mx0, 2));
                mx1 = fmaxf(mx1, __shfl_xor_sync(0xffffffffu, mx1, 1));
                mx1 = fmaxf(mx1, __shfl_xor_sync(0xffffffffu, mx1, 2));
                float mn0 = fmaxf(m[mt][0], mx0), mn1 = fmaxf(m[mt][1], mx1);
                float a0 = __expf(m[mt][0] - mn0), a1 = __expf(m[mt][1] - mn1);
                float sum0 = 0.f, sum1 = 0.f;
#pragma unroll
                for (int nt = 0; nt < 8; nt++) {
                    s[mt][nt][0] = __expf(s[mt][nt][0] - mn0);
                    s[mt][nt][1] = __expf(s[mt][nt][1] - mn0);
                    s[mt][nt][2] = __expf(s[mt][nt][2] - mn1);
                    s[mt][nt][3] = __expf(s[mt][nt][3] - mn1);
                    sum0 += s[mt][nt][0] + s[mt][nt][1];
                    sum1 += s[mt][nt][2] + s[mt][nt][3];
                }
                sum0 += __shfl_xor_sync(0xffffffffu, sum0, 1);
                sum0 += __shfl_xor_sync(0xffffffffu, sum0, 2);
                sum1 += __shfl_xor_sync(0xffffffffu, sum1, 1);
                sum1 += __shfl_xor_sync(0xffffffffu, sum1, 2);
                l[mt][0] = l[mt][0] * a0 + sum0;
                l[mt][1] = l[mt][1] * a1 + sum1;
                m[mt][0] = mn0;  m[mt][1] = mn1;
#pragma unroll
                for (int dt = 0; dt < 8; dt++) {
                    O[mt][dt][0] *= a0; O[mt][dt][1] *= a0;
                    O[mt][dt][2] *= a1; O[mt][dt][3] *= a1;
                }
            }

#pragma unroll
            for (int kk = 0; kk < 4; kk++) {
                uint32_t pah[2][4];
#pragma unroll
                for (int mt = 0; mt < 2; mt++)
#pragma unroll
                    for (int t = 0; t < 4; t++) {
                        float f0 = s[mt][2 * kk + (t >> 1)][(t & 1) * 2 + 0];
                        float f1 = s[mt][2 * kk + (t >> 1)][(t & 1) * 2 + 1];
                        pah[mt][t] = packh(f0, f1);
                    }
                const int vrow = kk * 16 + (lane & 7) + ((lane >> 3) & 1) * 8;
                const int voff = ((lane >> 4) & 1) * 16;
#pragma unroll
                for (int dp = 0; dp < 4; dp++) {
                    uint32_t vh4[4], vl4[4];
                    uint32_t a = kb + (uint32_t)(KVVAR + vrow * AST + dp * 32 + voff);
                    ldm_x4t(vh4, a);
                    ldm_x4t(vl4, a + KVVAR);
#pragma unroll
                    for (int mt = 0; mt < 2; mt++) {
                        mma_f16(O[mt][2 * dp],     pah[mt], vh4 + 0);
                        mma_f16(O[mt][2 * dp],     pah[mt], vl4 + 0);
                        mma_f16(O[mt][2 * dp + 1], pah[mt], vh4 + 2);
                        mma_f16(O[mt][2 * dp + 1], pah[mt], vl4 + 2);
                    }
                }
            }
        }
    }

    // epilogue: normalize, fp16 hi-only write [b][t][C]
    const int b = bh >> 4, h = bh & 15;
#pragma unroll
    for (int mt = 0; mt < 2; mt++) {
        const float inv0 = 1.f / l[mt][0], inv1 = 1.f / l[mt][1];
        const int i0 = iw + mt * 16 + (lane >> 2);
#pragma unroll
        for (int dt = 0; dt < 8; dt++) {
            const int col = h * 64 + dt * 8 + (lane & 3) * 2;
            {
                float f0 = O[mt][dt][0] * inv0, f1 = O[mt][dt][1] * inv0;
                size_t off = ((size_t)(b * T_SZ + i0)) * C_SZ + col;
                *(uint32_t*)(g_ao_hi + off) = packh(f0, f1);
            }
            {
                float f0 = O[mt][dt][2] * inv1, f1 = O[mt][dt][3] * inv1;
                size_t off = ((size_t)(b * T_SZ + i0 + 8)) * C_SZ + col;
                *(uint32_t*)(g_ao_hi + off) = packh(f0, f1);
            }
        }
    }
}

// ---------------------------------------------------------------------------
extern "C" void kernel_launch(void* const* d_in, const int* in_sizes, int n_in,
                              void* d_out, int out_size) {
    const float* x        = (const float*)d_in[0];
    const float* c_attn_w = (const float*)d_in[1];
    const float* c_attn_b = (const float*)d_in[2];
    const float* c_proj_w = (const float*)d_in[3];
    const float* c_proj_b = (const float*)d_in[4];
    float* out = (float*)d_out;

    prep_kernel<<<16384 + 3072 + 1024, 256>>>(x, c_attn_w, c_proj_w);

    cudaFuncSetAttribute(gemm_hmma,
                         cudaFuncAttributeMaxDynamicSharedMemorySize, GEMM_SMEM);
    cudaFuncSetAttribute(attn_hmma,
                         cudaFuncAttributeMaxDynamicSharedMemorySize, ATT_SMEM);

    // QKV: grid (24, 32)
    gemm_hmma<<<dim3(N_QKV / 128, M_ROWS / 128), 256, GEMM_SMEM>>>(
        c_attn_b, nullptr, 0);

    attn_hmma<<<dim3(32, T_SZ / 256), 256, ATT_SMEM>>>();

    // Proj: grid (8, 32)
    gemm_hmma<<<dim3(C_SZ / 128, M_ROWS / 128), 256, GEMM_SMEM>>>(
        c_proj_b, out, 1);
}

// round 13
// speedup vs baseline: 3.9290x; 1.1895x over previous
#include <cuda_runtime.h>
#include <cuda_fp16.h>
#include <cstdint>

#define B_SZ   2
#define T_SZ   2048
#define C_SZ   1024
#define M_ROWS 4096
#define N_QKV  3072
#define GEMM_K 1024

// ---------------------------------------------------------------------------
// Scratch (__device__ globals; no allocation allowed). All fp16 hi-only now.
// ---------------------------------------------------------------------------
__device__ __half g_x_hi[M_ROWS * C_SZ];
__device__ __half g_wq_hi[N_QKV * GEMM_K];     // transposed [n][k]
__device__ __half g_wp_hi[C_SZ * GEMM_K];      // transposed [n][k]
// qkv for attention: all hi-only; q pre-scaled by 1/8.  [bh][t][d]
__device__ __half g_k16h[32 * T_SZ * 64];
__device__ __half g_q16h[32 * T_SZ * 64];
__device__ __half g_v16h[32 * T_SZ * 64];
// attention out, fp16 hi only (proj A side), [b][t][C]
__device__ __half g_ao_hi[M_ROWS * C_SZ];

// ---------------------------------------------------------------------------
// PTX helpers (plain sm_103 target)
// ---------------------------------------------------------------------------
#define CP_ASYNC16(dst, src) \
    asm volatile("cp.async.cg.shared.global [%0], [%1], 16;" :: "r"(dst), "l"(src))
#define CP_COMMIT() asm volatile("cp.async.commit_group;" ::: "memory")
#define CP_WAIT1()  asm volatile("cp.async.wait_group 1;" ::: "memory")
#define CP_WAIT0()  asm volatile("cp.async.wait_group 0;" ::: "memory")

__device__ __forceinline__ void ldm_x4(uint32_t* r, uint32_t a) {
    asm volatile("ldmatrix.sync.aligned.m8n8.x4.shared.b16 {%0,%1,%2,%3}, [%4];"
                 : "=r"(r[0]), "=r"(r[1]), "=r"(r[2]), "=r"(r[3]) : "r"(a));
}
__device__ __forceinline__ void ldm_x4t(uint32_t* r, uint32_t a) {
    asm volatile("ldmatrix.sync.aligned.m8n8.x4.trans.shared.b16 {%0,%1,%2,%3}, [%4];"
                 : "=r"(r[0]), "=r"(r[1]), "=r"(r[2]), "=r"(r[3]) : "r"(a));
}
__device__ __forceinline__ void mma_f16(float* d, const uint32_t* a,
                                        const uint32_t* b) {
    asm volatile(
        "mma.sync.aligned.m16n8k16.row.col.f32.f16.f16.f32 "
        "{%0,%1,%2,%3}, {%4,%5,%6,%7}, {%8,%9}, {%0,%1,%2,%3};"
        : "+f"(d[0]), "+f"(d[1]), "+f"(d[2]), "+f"(d[3])
        : "r"(a[0]), "r"(a[1]), "r"(a[2]), "r"(a[3]), "r"(b[0]), "r"(b[1]));
}
__device__ __forceinline__ uint32_t packh(float f0, float f1) {
    __half2 t = __floats2half2_rn(f0, f1);
    return *reinterpret_cast<uint32_t*>(&t);
}

// ---------------------------------------------------------------------------
// Fused prep: x -> fp16; wq/wp -> transposed fp16.
// blocks [0,16384): x   [16384,19456): wq   [19456,20480): wp
// ---------------------------------------------------------------------------
__global__ __launch_bounds__(256)
void prep_kernel(const float* __restrict__ x,
                 const float* __restrict__ wq,
                 const float* __restrict__ wp) {
    __shared__ float tile[32][33];
    const int blk = blockIdx.x;
    const int tid = threadIdx.x;

    if (blk < 16384) {
        int i = blk * 256 + tid;
        g_x_hi[i] = __float2half_rn(x[i]);
        return;
    }

    const float* w;
    __half* oh;
    int N, bb;
    if (blk < 16384 + 3072) {
        bb = blk - 16384; w = wq; oh = g_wq_hi; N = N_QKV;
    } else {
        bb = blk - 19456; w = wp; oh = g_wp_hi; N = C_SZ;
    }
    const int nb = (bb % (N / 32)) * 32;
    const int kb = (bb / (N / 32)) * 32;
    const int tx = tid & 31, ty = tid >> 5;
#pragma unroll
    for (int i2 = 0; i2 < 32; i2 += 8)
        tile[ty + i2][tx] = w[(size_t)(kb + ty + i2) * N + nb + tx];
    __syncthreads();
#pragma unroll
    for (int i2 = 0; i2 < 32; i2 += 8)
        oh[(size_t)(nb + ty + i2) * GEMM_K + kb + tx] =
            __float2half_rn(tile[tx][ty + i2]);
}

// ---------------------------------------------------------------------------
// HMMA 1-pass fp16 GEMM: C = Ah @ Bh^T.  128x128 CTA tile, BK=64, 3-stage
// cp.async, 256 threads (8 warps 4x2, warp 32x64), 2 CTAs/SM.
// mode 0: bias + fp16 scatter (k hi, q hi*0.125, v hi)
// mode 1: bias + fp32 store
// ---------------------------------------------------------------------------
#define G_ROWB   144                    // 128B data + 16B pad
#define G_TILE   (128 * G_ROWB)         // 18432
#define G_STAGE  (2 * G_TILE)           // 36864 (Ah, Bh)
#define GEMM_SMEM (3 * G_STAGE)         // 110592 -> 2 CTAs/SM

__global__ __launch_bounds__(256, 2)
void gemm_hmma(const float* __restrict__ bias, float* __restrict__ out,
               int mode) {
    extern __shared__ char smem[];
    const uint32_t sbase = (uint32_t)__cvta_generic_to_shared(smem);
    const int tid = threadIdx.x;
    const int lane = tid & 31, warp = tid >> 5;
    const int wr = warp & 3, wc = warp >> 2;      // 4x2 warp grid, warp 32x64
    const int rowBase = blockIdx.y * 128;
    const int colBase = blockIdx.x * 128;

    const __half* srcs[2];
    if (mode == 0) { srcs[0] = g_x_hi;  srcs[1] = g_wq_hi; }
    else           { srcs[0] = g_ao_hi; srcs[1] = g_wp_hi; }
    const int rbase[2] = {rowBase, colBase};

    float acc[2][8][4];
#pragma unroll
    for (int mt = 0; mt < 2; mt++)
#pragma unroll
        for (int nt = 0; nt < 8; nt++)
#pragma unroll
            for (int q = 0; q < 4; q++) acc[mt][nt][q] = 0.f;

    auto prefetch = [&](int chunk) {
        const int st = chunk % 3;
        const int k0 = chunk * 64;
#pragma unroll
        for (int v = 0; v < 2; v++) {
#pragma unroll
            for (int it = 0; it < 4; it++) {
                int p = tid + it * 256;            // 0..1023
                int r = p >> 3, cp = p & 7;
                const __half* g =
                    srcs[v] + (size_t)(rbase[v] + r) * GEMM_K + k0 + cp * 8;
                uint32_t d = sbase + (uint32_t)(st * G_STAGE + v * G_TILE
                                                + r * G_ROWB + cp * 16);
                CP_ASYNC16(d, g);
            }
        }
        CP_COMMIT();
    };

    prefetch(0);
    prefetch(1);

    const int NC = GEMM_K / 64;          // 16
    for (int c = 0; c < NC; c++) {
        if (c + 1 < NC) { CP_WAIT1(); } else { CP_WAIT0(); }
        __syncthreads();
        if (c + 2 < NC) prefetch(c + 2);  // writes stage (c+2)%3 = (c-1)%3: safe

        const uint32_t bufBase = sbase + (uint32_t)((c % 3) * G_STAGE);
#pragma unroll
        for (int s = 0; s < 4; s++) {
            uint32_t ah[2][4], bh[4][4];
            const int akb = s * 32 + ((lane >> 4) & 1) * 16;
            const int arow = wr * 32 + (lane & 7) + ((lane >> 3) & 1) * 8;
            ldm_x4(ah[0], bufBase + (uint32_t)(arow * G_ROWB + akb));
            ldm_x4(ah[1], bufBase + (uint32_t)((arow + 16) * G_ROWB + akb));

            const int bkb = s * 32 + ((lane >> 3) & 1) * 16;
            const int brow = wc * 64 + ((lane >> 4) & 1) * 8 + (lane & 7);
#pragma unroll
            for (int p2 = 0; p2 < 4; p2++)
                ldm_x4(bh[p2], bufBase + (uint32_t)(G_TILE + (brow + p2 * 16) * G_ROWB + bkb));

#pragma unroll
            for (int mt = 0; mt < 2; mt++)
#pragma unroll
                for (int nt = 0; nt < 8; nt++)
                    mma_f16(acc[mt][nt], ah[mt], &bh[nt >> 1][(nt & 1) * 2]);
        }
    }

    const int r0 = lane >> 2;
    const int c0 = (lane & 3) * 2;
#pragma unroll
    for (int mt = 0; mt < 2; mt++) {
#pragma unroll
        for (int nt = 0; nt < 8; nt++) {
            const int n0 = colBase + wc * 64 + nt * 8 + c0;
            const float b0 = bias[n0], b1 = bias[n0 + 1];
#pragma unroll
            for (int half = 0; half < 2; half++) {
                const int m = rowBase + wr * 32 + mt * 16 + r0 + half * 8;
                float f0 = acc[mt][nt][half * 2 + 0] + b0;
                float f1 = acc[mt][nt][half * 2 + 1] + b1;
                if (mode == 0) {
                    const int bb = m >> 11, t = m & 2047;
                    const int sec = n0 >> 10, cc = n0 & 1023;
                    const int h = cc >> 6, d0 = cc & 63;
                    size_t off = (((size_t)(bb * 16 + h)) * T_SZ + t) * 64 + d0;
                    if (sec == 1) {
                        *(uint32_t*)(g_q16h + off) = packh(f0 * 0.125f, f1 * 0.125f);
                    } else {
                        __half* dh = (sec == 0) ? g_k16h : g_v16h;
                        *(uint32_t*)(dh + off) = packh(f0, f1);
                    }
                } else {
                    float2 v; v.x = f0; v.y = f1;
                    *(float2*)(out + (size_t)m * C_SZ + n0) = v;
                }
            }
        }
    }
}

// ---------------------------------------------------------------------------
// Flash attention v5: fully 1-pass fp16. 256-row i-tiles, 8 warps x 32 rows.
// wei = K@Q^T: query-role = k (hi, resident), key-role = q (hi, pre-scaled).
// S = Kh·Qh;  O = Ph·Vh.  Streams q-hi + v-hi only.
// ---------------------------------------------------------------------------
#define AST   144
#define SQH_O 0
#define SKV_O (256 * AST)              // 36864
#define KVVAR (64 * AST)               // 9216
#define KVBUF (2 * KVVAR)              // 18432 (qh, vh)
#define ATT_SMEM (SKV_O + 2 * KVBUF)   // 73728

__global__ __launch_bounds__(256, 1)
void attn_hmma() {
    extern __shared__ char smem[];
    const uint32_t sbase = (uint32_t)__cvta_generic_to_shared(smem);
    const int tid = threadIdx.x;
    const int lane = tid & 31, w = tid >> 5;
    const int bh = blockIdx.x;
    const int it = (int)(gridDim.y - 1 - blockIdx.y);   // heavy blocks first

    const size_t hbo = (size_t)bh * T_SZ * 64;
    const __half* kvsrc[2] = {g_q16h + hbo, g_v16h + hbo};

    auto prefetchKV = [&](int jt) {
        const int buf = jt & 1;
#pragma unroll
        for (int i = 0; i < 4; i++) {
            int p = tid + i * 256;               // 0..1023
            int v = p >> 9, rem = p & 511;
            int r = rem >> 3, cp = rem & 7;
            const __half* src = kvsrc[v] + (size_t)(jt * 64 + r) * 64 + cp * 8;
            uint32_t dst = sbase + (uint32_t)(SKV_O + buf * KVBUF + v * KVVAR
                                              + r * AST + cp * 16);
            CP_ASYNC16(dst, src);
        }
        CP_COMMIT();
    };

    prefetchKV(0);

    // resident query-role tile (k hi)
    {
        const __half* kh = g_k16h + hbo;
        for (int p = tid; p < 256 * 32; p += 256) {
            int r = p >> 5, c2 = p & 31;
            size_t go = (size_t)(it * 256 + r) * 64 + c2 * 2;
            *(uint32_t*)(smem + SQH_O + r * AST + c2 * 4) = *(const uint32_t*)(kh + go);
        }
    }
    __syncthreads();

    float m[2][2], l[2][2];
#pragma unroll
    for (int mt = 0; mt < 2; mt++) { m[mt][0] = m[mt][1] = -1e30f; l[mt][0] = l[mt][1] = 0.f; }
    float O[2][8][4];
#pragma unroll
    for (int mt = 0; mt < 2; mt++)
#pragma unroll
        for (int dt = 0; dt < 8; dt++)
#pragma unroll
            for (int q = 0; q < 4; q++) O[mt][dt][q] = 0.f;

    const int iw = it * 256 + w * 32;
    const int jlast = 4 * it + 3;

    for (int jt = 0; jt <= jlast; jt++) {
        CP_WAIT0();
        __syncthreads();
        if (jt < jlast) prefetchKV(jt + 1);

        if (jt * 64 <= iw + 31) {
            const uint32_t kb = sbase + (uint32_t)(SKV_O + (jt & 1) * KVBUF);
            float s[2][8][4];
#pragma unroll
            for (int mt = 0; mt < 2; mt++)
#pragma unroll
                for (int nt = 0; nt < 8; nt++)
#pragma unroll
                    for (int q = 0; q < 4; q++) s[mt][nt][q] = 0.f;

            // ---- scores: S = Kh @ Qh^T (1 pass) ----
#pragma unroll
            for (int kk = 0; kk < 4; kk++) {
                uint32_t ah[2][4];
                const int ab = kk * 32 + ((lane >> 4) & 1) * 16;
                const int arow = w * 32 + (lane & 7) + ((lane >> 3) & 1) * 8;
                ldm_x4(ah[0], sbase + (uint32_t)(SQH_O + arow * AST + ab));
                ldm_x4(ah[1], sbase + (uint32_t)(SQH_O + (arow + 16) * AST + ab));

                const int bb = kk * 32 + ((lane >> 3) & 1) * 16;
                const int br = ((lane >> 4) & 1) * 8 + (lane & 7);
#pragma unroll
                for (int np = 0; np < 4; np++) {
                    uint32_t qf[4];
                    ldm_x4(qf, kb + (uint32_t)((np * 16 + br) * AST + bb));
#pragma unroll
                    for (int mt = 0; mt < 2; mt++) {
                        mma_f16(s[mt][2 * np],     ah[mt], qf + 0);
                        mma_f16(s[mt][2 * np + 1], ah[mt], qf + 2);
                    }
                }
            }

            // ---- causal mask ----
            const int i0 = iw + (lane >> 2);
            if (jt * 64 + 63 > iw) {
#pragma unroll
                for (int mt = 0; mt < 2; mt++)
#pragma unroll
                    for (int nt = 0; nt < 8; nt++)
#pragma unroll
                        for (int q = 0; q < 4; q++) {
                            int j = jt * 64 + nt * 8 + (lane & 3) * 2 + (q & 1);
                            int i = i0 + mt * 16 + ((q >> 1) ? 8 : 0);
                            if (j > i) s[mt][nt][q] = -1e30f;
                        }
            }

            // ---- online softmax ----
#pragma unroll
            for (int mt = 0; mt < 2; mt++) {
                float mx0 = -1e30f, mx1 = -1e30f;
#pragma unroll
                for (int nt = 0; nt < 8; nt++) {
                    mx0 = fmaxf(mx0, fmaxf(s[mt][nt][0], s[mt][nt][1]));
                    mx1 = fmaxf(mx1, fmaxf(s[mt][nt][2], s[mt][nt][3]));
                }
                mx0 = fmaxf(mx0, __shfl_xor_sync(0xffffffffu, mx0, 1));
                mx0 = fmaxf(mx0, __shfl_xor_sync(0xffffffffu, mx0, 2));
                mx1 = fmaxf(mx1, __shfl_xor_sync(0xffffffffu, mx1, 1));
                mx1 = fmaxf(mx1, __shfl_xor_sync(0xffffffffu, mx1, 2));
                float mn0 = fmaxf(m[mt][0], mx0), mn1 = fmaxf(m[mt][1], mx1);
                float a0 = __expf(m[mt][0] - mn0), a1 = __expf(m[mt][1] - mn1);
                float sum0 = 0.f, sum1 = 0.f;
#pragma unroll
                for (int nt = 0; nt < 8; nt++) {
                    s[mt][nt][0] = __expf(s[mt][nt][0] - mn0);
                    s[mt][nt][1] = __expf(s[mt][nt][1] - mn0);
                    s[mt][nt][2] = __expf(s[mt][nt][2] - mn1);
                    s[mt][nt][3] = __expf(s[mt][nt][3] - mn1);
                    sum0 += s[mt][nt][0] + s[mt][nt][1];
                    sum1 += s[mt][nt][2] + s[mt][nt][3];
                }
                sum0 += __shfl_xor_sync(0xffffffffu, sum0, 1);
                sum0 += __shfl_xor_sync(0xffffffffu, sum0, 2);
                sum1 += __shfl_xor_sync(0xffffffffu, sum1, 1);
                sum1 += __shfl_xor_sync(0xffffffffu, sum1, 2);
                l[mt][0] = l[mt][0] * a0 + sum0;
                l[mt][1] = l[mt][1] * a1 + sum1;
                m[mt][0] = mn0;  m[mt][1] = mn1;
#pragma unroll
                for (int dt = 0; dt < 8; dt++) {
                    O[mt][dt][0] *= a0; O[mt][dt][1] *= a0;
                    O[mt][dt][2] *= a1; O[mt][dt][3] *= a1;
                }
            }

            // ---- PV: O += Ph @ Vh (1 pass) ----
#pragma unroll
            for (int kk = 0; kk < 4; kk++) {
                uint32_t pah[2][4];
#pragma unroll
                for (int mt = 0; mt < 2; mt++)
#pragma unroll
                    for (int t = 0; t < 4; t++) {
                        float f0 = s[mt][2 * kk + (t >> 1)][(t & 1) * 2 + 0];
                        float f1 = s[mt][2 * kk + (t >> 1)][(t & 1) * 2 + 1];
                        pah[mt][t] = packh(f0, f1);
                    }
                const int vrow = kk * 16 + (lane & 7) + ((lane >> 3) & 1) * 8;
                const int voff = ((lane >> 4) & 1) * 16;
#pragma unroll
                for (int dp = 0; dp < 4; dp++) {
                    uint32_t vh4[4];
                    ldm_x4t(vh4, kb + (uint32_t)(KVVAR + vrow * AST + dp * 32 + voff));
#pragma unroll
                    for (int mt = 0; mt < 2; mt++) {
                        mma_f16(O[mt][2 * dp],     pah[mt], vh4 + 0);
                        mma_f16(O[mt][2 * dp + 1], pah[mt], vh4 + 2);
                    }
                }
            }
        }
    }

    // epilogue: normalize, fp16 write [b][t][C]
    const int b = bh >> 4, h = bh & 15;
#pragma unroll
    for (int mt = 0; mt < 2; mt++) {
        const float inv0 = 1.f / l[mt][0], inv1 = 1.f / l[mt][1];
        const int i0 = iw + mt * 16 + (lane >> 2);
#pragma unroll
        for (int dt = 0; dt < 8; dt++) {
            const int col = h * 64 + dt * 8 + (lane & 3) * 2;
            {
                float f0 = O[mt][dt][0] * inv0, f1 = O[mt][dt][1] * inv0;
                size_t off = ((size_t)(b * T_SZ + i0)) * C_SZ + col;
                *(uint32_t*)(g_ao_hi + off) = packh(f0, f1);
            }
            {
                float f0 = O[mt][dt][2] * inv1, f1 = O[mt][dt][3] * inv1;
                size_t off = ((size_t)(b * T_SZ + i0 + 8)) * C_SZ + col;
                *(uint32_t*)(g_ao_hi + off) = packh(f0, f1);
            }
        }
    }
}

// ---------------------------------------------------------------------------
extern "C" void kernel_launch(void* const* d_in, const int* in_sizes, int n_in,
                              void* d_out, int out_size) {
    const float* x        = (const float*)d_in[0];
    const float* c_attn_w = (const float*)d_in[1];
    const float* c_attn_b = (const float*)d_in[2];
    const float* c_proj_w = (const float*)d_in[3];
    const float* c_proj_b = (const float*)d_in[4];
    float* out = (float*)d_out;

    prep_kernel<<<16384 + 3072 + 1024, 256>>>(x, c_attn_w, c_proj_w);

    cudaFuncSetAttribute(gemm_hmma,
                         cudaFuncAttributeMaxDynamicSharedMemorySize, GEMM_SMEM);
    cudaFuncSetAttribute(attn_hmma,
                         cudaFuncAttributeMaxDynamicSharedMemorySize, ATT_SMEM);

    // QKV: grid (24, 32)
    gemm_hmma<<<dim3(N_QKV / 128, M_ROWS / 128), 256, GEMM_SMEM>>>(
        c_attn_b, nullptr, 0);

    attn_hmma<<<dim3(32, T_SZ / 256), 256, ATT_SMEM>>>();

    // Proj: grid (8, 32)
    gemm_hmma<<<dim3(C_SZ / 128, M_ROWS / 128), 256, GEMM_SMEM>>>(
        c_proj_b, out, 1);
}